// round 10
// baseline (speedup 1.0000x reference)
#include <cuda_runtime.h>
#include <cuda_bf16.h>
#include <math_constants.h>

// Fixed problem shapes
#define B_ 2
#define T_ 2048
#define D_ 1024
#define H_ 16
#define HD_ 64
#define NTOK (B_ * T_)          // 4096
#define MQKV (3 * D_)           // 3072
#define K_ 1024

// Scratch (allocation-free rule: __device__ globals)
__device__ float g_qkv[NTOK * MQKV];                       // [4096, 3072] fp32 q|k|v

// bf16 hi/lo split scratch
__device__ __nv_bfloat16 g_xhi[NTOK * K_],  g_xlo[NTOK * K_];
__device__ __nv_bfloat16 g_wqhi[MQKV * K_], g_wqlo[MQKV * K_];
__device__ __nv_bfloat16 g_wohi[D_ * K_],   g_wolo[D_ * K_];
__device__ __nv_bfloat16 g_chi[NTOK * K_],  g_clo[NTOK * K_];   // ctx hi/lo (flash output)

// ---------------------------------------------------------------------------
// helpers
// ---------------------------------------------------------------------------
__device__ __forceinline__ void split2(float x, float y, unsigned &hi, unsigned &lo)
{
    __nv_bfloat16 hx = __float2bfloat16(x), hy = __float2bfloat16(y);
    __nv_bfloat162 h(hx, hy);
    __nv_bfloat162 l(__float2bfloat16(x - __bfloat162float(hx)),
                     __float2bfloat16(y - __bfloat162float(hy)));
    hi = *(unsigned*)&h;
    lo = *(unsigned*)&l;
}

__device__ __forceinline__ void mma16816(float c[4], const unsigned a[4], const unsigned b[2])
{
    asm volatile(
        "mma.sync.aligned.m16n8k16.row.col.f32.bf16.bf16.f32 "
        "{%0,%1,%2,%3}, {%4,%5,%6,%7}, {%8,%9}, {%0,%1,%2,%3};\n"
        : "+f"(c[0]), "+f"(c[1]), "+f"(c[2]), "+f"(c[3])
        : "r"(a[0]), "r"(a[1]), "r"(a[2]), "r"(a[3]), "r"(b[0]), "r"(b[1]));
}

__device__ __forceinline__ unsigned sptr(const void* p)
{
    return (unsigned)__cvta_generic_to_shared(p);
}

__device__ __forceinline__ void ldsm_x4(unsigned r[4], unsigned addr)
{
    asm volatile("ldmatrix.sync.aligned.m8n8.x4.shared.b16 {%0,%1,%2,%3}, [%4];"
        : "=r"(r[0]), "=r"(r[1]), "=r"(r[2]), "=r"(r[3]) : "r"(addr));
}

__device__ __forceinline__ void ldsm_x2(unsigned r[2], unsigned addr)
{
    asm volatile("ldmatrix.sync.aligned.m8n8.x2.shared.b16 {%0,%1}, [%2];"
        : "=r"(r[0]), "=r"(r[1]) : "r"(addr));
}

// ---------------------------------------------------------------------------
// Split fp32 -> bf16 hi + bf16 lo (residual). Vectorized by 4.
// ---------------------------------------------------------------------------
__global__ __launch_bounds__(256) void split_bf16(
    const float* __restrict__ in, __nv_bfloat16* __restrict__ hi,
    __nv_bfloat16* __restrict__ lo, int n4)
{
    int i = blockIdx.x * 256 + threadIdx.x;
    if (i >= n4) return;
    float4 v = ((const float4*)in)[i];
    unsigned h0, l0, h1, l1;
    split2(v.x, v.y, h0, l0);
    split2(v.z, v.w, h1, l1);
    ((unsigned*)hi)[i * 2 + 0] = h0;
    ((unsigned*)hi)[i * 2 + 1] = h1;
    ((unsigned*)lo)[i * 2 + 0] = l0;
    ((unsigned*)lo)[i * 2 + 1] = l1;
}

// ---------------------------------------------------------------------------
// Tensor-core NT GEMM, bf16x3 split: C[N,M] = A[N,K] @ W[M,K]^T in ~fp32 prec.
// mma.sync.m16n8k16.bf16 with ldmatrix fragment loads.
// Block 128x128, BK=32, 8 warps, warp tile 64x32.
// ---------------------------------------------------------------------------
#define BM 128
#define BN 128
#define BK 32
#define SSTR 40   // 80B row stride: LDSM phases hit banks {0,20,8,28,16,4,24,12}

__global__ __launch_bounds__(256) void gemm_bf16x3(
    const __nv_bfloat16* __restrict__ Ahi, const __nv_bfloat16* __restrict__ Alo,
    const __nv_bfloat16* __restrict__ Whi, const __nv_bfloat16* __restrict__ Wlo,
    float* __restrict__ C, int Mcols)
{
    __shared__ __nv_bfloat16 sAhi[BM][SSTR], sAlo[BM][SSTR];
    __shared__ __nv_bfloat16 sBhi[BN][SSTR], sBlo[BN][SSTR];

    const int tid  = threadIdx.x;
    const int warp = tid >> 5;
    const int lane = tid & 31;
    const int wm = warp >> 2;
    const int wn = warp & 3;
    const int g  = lane >> 2;
    const int tg = lane & 3;
    const int rowBase = blockIdx.y * BM;
    const int colBase = blockIdx.x * BN;

    // ldmatrix per-lane address components
    const int aq   = lane >> 3;                       // quadrant 0..3
    const int arow0 = wm * 64 + (aq & 1) * 8 + (lane & 7);
    const int acolq = (aq >> 1) * 8;
    const int l16  = lane & 15;
    const int brow0 = wn * 32 + (l16 & 7);
    const int bcolq = (l16 >> 3) * 8;

    float acc[4][4][4];
#pragma unroll
    for (int im = 0; im < 4; im++)
#pragma unroll
        for (int in = 0; in < 4; in++)
#pragma unroll
            for (int q = 0; q < 4; q++) acc[im][in][q] = 0.f;

    uint4 pAh[2], pAl[2], pBh[2], pBl[2];

#pragma unroll
    for (int l = 0; l < 2; l++) {
        int idx = l * 256 + tid;
        int r = idx >> 2, c8 = (idx & 3) * 8;
        pAh[l] = *(const uint4*)(Ahi + (size_t)(rowBase + r) * K_ + c8);
        pAl[l] = *(const uint4*)(Alo + (size_t)(rowBase + r) * K_ + c8);
        pBh[l] = *(const uint4*)(Whi + (size_t)(colBase + r) * K_ + c8);
        pBl[l] = *(const uint4*)(Wlo + (size_t)(colBase + r) * K_ + c8);
    }

    for (int k0 = 0; k0 < K_; k0 += BK) {
#pragma unroll
        for (int l = 0; l < 2; l++) {
            int idx = l * 256 + tid;
            int r = idx >> 2, c8 = (idx & 3) * 8;
            *(uint4*)&sAhi[r][c8] = pAh[l];
            *(uint4*)&sAlo[r][c8] = pAl[l];
            *(uint4*)&sBhi[r][c8] = pBh[l];
            *(uint4*)&sBlo[r][c8] = pBl[l];
        }
        __syncthreads();

        if (k0 + BK < K_) {
#pragma unroll
            for (int l = 0; l < 2; l++) {
                int idx = l * 256 + tid;
                int r = idx >> 2, c8 = (idx & 3) * 8;
                pAh[l] = *(const uint4*)(Ahi + (size_t)(rowBase + r) * K_ + k0 + BK + c8);
                pAl[l] = *(const uint4*)(Alo + (size_t)(rowBase + r) * K_ + k0 + BK + c8);
                pBh[l] = *(const uint4*)(Whi + (size_t)(colBase + r) * K_ + k0 + BK + c8);
                pBl[l] = *(const uint4*)(Wlo + (size_t)(colBase + r) * K_ + k0 + BK + c8);
            }
        }

#pragma unroll
        for (int ks = 0; ks < BK; ks += 16) {
            unsigned ahi[4][4], alo[4][4], bhi[4][2], blo[4][2];
#pragma unroll
            for (int im = 0; im < 4; im++) {
                ldsm_x4(ahi[im], sptr(&sAhi[arow0 + im * 16][ks + acolq]));
                ldsm_x4(alo[im], sptr(&sAlo[arow0 + im * 16][ks + acolq]));
            }
#pragma unroll
            for (int in = 0; in < 4; in++) {
                ldsm_x2(bhi[in], sptr(&sBhi[brow0 + in * 8][ks + bcolq]));
                ldsm_x2(blo[in], sptr(&sBlo[brow0 + in * 8][ks + bcolq]));
            }
#pragma unroll
            for (int im = 0; im < 4; im++)
#pragma unroll
                for (int in = 0; in < 4; in++) {
                    mma16816(acc[im][in], ahi[im], bhi[in]);
                    mma16816(acc[im][in], ahi[im], blo[in]);
                    mma16816(acc[im][in], alo[im], bhi[in]);
                }
        }
        __syncthreads();
    }

#pragma unroll
    for (int im = 0; im < 4; im++) {
#pragma unroll
        for (int in = 0; in < 4; in++) {
            int row = rowBase + wm * 64 + im * 16 + g;
            int col = colBase + wn * 32 + in * 8 + tg * 2;
            float2 v01 = make_float2(acc[im][in][0], acc[im][in][1]);
            float2 v23 = make_float2(acc[im][in][2], acc[im][in][3]);
            *(float2*)(C + (size_t)row * Mcols + col)       = v01;
            *(float2*)(C + (size_t)(row + 8) * Mcols + col) = v23;
        }
    }
}

// ---------------------------------------------------------------------------
// Fused flash attention: scores (scale+ALiBi+causal) + online softmax + P@V.
// Block = 128 q-rows (8 warps x 16 rows), j-tiles of 64.
// QK^T and P@V via mma.m16n8k16.bf16 (hi/lo x3), ldmatrix for K/V fragments.
// ---------------------------------------------------------------------------
#define FSTR 72   // 144B row stride: LDSM phases hit banks {0,4,...,28}

__global__ __launch_bounds__(256, 1) void flash_kernel(
    const float* __restrict__ qkv,
    __nv_bfloat16* __restrict__ chi, __nv_bfloat16* __restrict__ clo)
{
    __shared__ __nv_bfloat16 sKhi[64][FSTR], sKlo[64][FSTR];
    __shared__ __nv_bfloat16 sVhi[64][FSTR], sVlo[64][FSTR];   // transposed: [e][j]

    const int iblk = (int)gridDim.x - 1 - (int)blockIdx.x;  // big tiles first
    const int bh   = blockIdx.y;
    const int b    = bh >> 4;
    const int h    = bh & 15;
    const int tid  = threadIdx.x;
    const int warp = tid >> 5;
    const int lane = tid & 31;
    const int g    = lane >> 2;
    const int tg   = lane & 3;
    const int rbase = iblk * 128 + warp * 16;               // batch-local q-row base of warp
    const float slope = exp2f(-(float)(h + 1) / 16.f);

    // ldmatrix x2 per-lane address components (B operand pattern)
    const int l16   = lane & 15;
    const int brow0 = l16 & 7;
    const int bcolq = (l16 >> 3) * 8;

    const float* qkbase = qkv + (size_t)(b * T_) * MQKV + h * HD_;

    // Q fragments straight from gmem fp32 (once per block), hi/lo split
    unsigned qhi[4][4], qlo[4][4];
#pragma unroll
    for (int kb = 0; kb < 4; kb++)
#pragma unroll
        for (int r = 0; r < 4; r++) {
            int row = rbase + g + (r & 1) * 8;
            int col = kb * 16 + tg * 2 + (r >> 1) * 8;
            float2 v = *(const float2*)(qkbase + (size_t)row * MQKV + col);
            split2(v.x, v.y, qhi[kb][r], qlo[kb][r]);
        }

    float acc_o[8][4];
#pragma unroll
    for (int nf = 0; nf < 8; nf++)
#pragma unroll
        for (int q = 0; q < 4; q++) acc_o[nf][q] = 0.f;
    float m0 = -CUDART_INF_F, m1 = -CUDART_INF_F;
    float l0 = 0.f, l1 = 0.f;

    const int gi0 = rbase + g;
    const int gi1 = gi0 + 8;
    const int jt_max = (iblk * 128 + 127) >> 6;

    const int ldj  = tid >> 4;              // 0..15 base row (stride 16 over 4 its)
    const int lde4 = (tid & 15) * 4;        // element-4 column

    for (int jt = 0; jt <= jt_max; jt++) {
        // load K (row layout) and V (transposed) tiles, fp32 -> bf16 hi/lo
        const float* tilebase = qkbase + (size_t)(jt * 64) * MQKV;
#pragma unroll
        for (int it = 0; it < 4; it++) {
            int j = it * 16 + ldj;
            const float* src = tilebase + (size_t)j * MQKV;
            float4 kv = *(const float4*)(src + D_ + lde4);
            unsigned kh0, kl0, kh1, kl1;
            split2(kv.x, kv.y, kh0, kl0);
            split2(kv.z, kv.w, kh1, kl1);
            *(unsigned*)&sKhi[j][lde4]     = kh0;
            *(unsigned*)&sKhi[j][lde4 + 2] = kh1;
            *(unsigned*)&sKlo[j][lde4]     = kl0;
            *(unsigned*)&sKlo[j][lde4 + 2] = kl1;

            float4 vv = *(const float4*)(src + 2 * D_ + lde4);
            float vf[4] = {vv.x, vv.y, vv.z, vv.w};
#pragma unroll
            for (int q = 0; q < 4; q++) {
                __nv_bfloat16 hb = __float2bfloat16(vf[q]);
                sVhi[lde4 + q][j] = hb;
                sVlo[lde4 + q][j] = __float2bfloat16(vf[q] - __bfloat162float(hb));
            }
        }
        __syncthreads();

        if (jt * 64 <= rbase + 15) {
            // --- S = Q K^T (bf16x3) ---
            float s[8][4];
#pragma unroll
            for (int nf = 0; nf < 8; nf++)
#pragma unroll
                for (int q = 0; q < 4; q++) s[nf][q] = 0.f;

#pragma unroll
            for (int kb = 0; kb < 4; kb++) {
                const int c0 = kb * 16 + bcolq;
#pragma unroll
                for (int nf = 0; nf < 8; nf++) {
                    unsigned kbh[2], kbl[2];
                    ldsm_x2(kbh, sptr(&sKhi[nf * 8 + brow0][c0]));
                    ldsm_x2(kbl, sptr(&sKlo[nf * 8 + brow0][c0]));
                    mma16816(s[nf], qhi[kb], kbh);
                    mma16816(s[nf], qlo[kb], kbh);
                    mma16816(s[nf], qhi[kb], kbl);
                }
            }

            // --- scale + ALiBi + causal mask ---
#pragma unroll
            for (int nf = 0; nf < 8; nf++) {
                int j0 = jt * 64 + nf * 8 + tg * 2;
                s[nf][0] = (j0     <= gi0) ? s[nf][0] * 0.125f + slope * (float)(j0     - gi0) : -CUDART_INF_F;
                s[nf][1] = (j0 + 1 <= gi0) ? s[nf][1] * 0.125f + slope * (float)(j0 + 1 - gi0) : -CUDART_INF_F;
                s[nf][2] = (j0     <= gi1) ? s[nf][2] * 0.125f + slope * (float)(j0     - gi1) : -CUDART_INF_F;
                s[nf][3] = (j0 + 1 <= gi1) ? s[nf][3] * 0.125f + slope * (float)(j0 + 1 - gi1) : -CUDART_INF_F;
            }

            // --- online softmax update ---
            float tm0 = -CUDART_INF_F, tm1 = -CUDART_INF_F;
#pragma unroll
            for (int nf = 0; nf < 8; nf++) {
                tm0 = fmaxf(tm0, fmaxf(s[nf][0], s[nf][1]));
                tm1 = fmaxf(tm1, fmaxf(s[nf][2], s[nf][3]));
            }
            tm0 = fmaxf(tm0, __shfl_xor_sync(0xffffffffu, tm0, 1));
            tm0 = fmaxf(tm0, __shfl_xor_sync(0xffffffffu, tm0, 2));
            tm1 = fmaxf(tm1, __shfl_xor_sync(0xffffffffu, tm1, 1));
            tm1 = fmaxf(tm1, __shfl_xor_sync(0xffffffffu, tm1, 2));
            float mn0 = fmaxf(m0, tm0), mn1 = fmaxf(m1, tm1);
            float a0 = __expf(m0 - mn0), a1 = __expf(m1 - mn1);

            float sum0 = 0.f, sum1 = 0.f;
#pragma unroll
            for (int nf = 0; nf < 8; nf++) {
                s[nf][0] = __expf(s[nf][0] - mn0);
                s[nf][1] = __expf(s[nf][1] - mn0);
                s[nf][2] = __expf(s[nf][2] - mn1);
                s[nf][3] = __expf(s[nf][3] - mn1);
                sum0 += s[nf][0] + s[nf][1];
                sum1 += s[nf][2] + s[nf][3];
            }
            sum0 += __shfl_xor_sync(0xffffffffu, sum0, 1);
            sum0 += __shfl_xor_sync(0xffffffffu, sum0, 2);
            sum1 += __shfl_xor_sync(0xffffffffu, sum1, 1);
            sum1 += __shfl_xor_sync(0xffffffffu, sum1, 2);
            l0 = l0 * a0 + sum0;
            l1 = l1 * a1 + sum1;
            m0 = mn0; m1 = mn1;

#pragma unroll
            for (int nf = 0; nf < 8; nf++) {
                acc_o[nf][0] *= a0; acc_o[nf][1] *= a0;
                acc_o[nf][2] *= a1; acc_o[nf][3] *= a1;
            }

            // --- O += P @ V : S-accum frags feed A operand directly ---
#pragma unroll
            for (int kb = 0; kb < 4; kb++) {
                unsigned pah[4], pal[4];
                split2(s[2 * kb][0],     s[2 * kb][1],     pah[0], pal[0]);
                split2(s[2 * kb][2],     s[2 * kb][3],     pah[1], pal[1]);
                split2(s[2 * kb + 1][0], s[2 * kb + 1][1], pah[2], pal[2]);
                split2(s[2 * kb + 1][2], s[2 * kb + 1][3], pah[3], pal[3]);
                const int c0 = kb * 16 + bcolq;
#pragma unroll
                for (int nf = 0; nf < 8; nf++) {
                    unsigned vbh[2], vbl[2];
                    ldsm_x2(vbh, sptr(&sVhi[nf * 8 + brow0][c0]));
                    ldsm_x2(vbl, sptr(&sVlo[nf * 8 + brow0][c0]));
                    mma16816(acc_o[nf], pah, vbh);
                    mma16816(acc_o[nf], pal, vbh);
                    mma16816(acc_o[nf], pah, vbl);
                }
            }
        }
        __syncthreads();
    }

    // --- epilogue: O /= l, write ctx as bf16 hi/lo ---
    const float r0 = 1.f / l0, r1 = 1.f / l1;
    const size_t base0 = (size_t)(b * T_ + gi0) * D_ + h * HD_;
    const size_t base1 = base0 + (size_t)8 * D_;
#pragma unroll
    for (int nf = 0; nf < 8; nf++) {
        int col = nf * 8 + tg * 2;
        unsigned uh, ul;
        split2(acc_o[nf][0] * r0, acc_o[nf][1] * r0, uh, ul);
        *(unsigned*)(chi + base0 + col) = uh;
        *(unsigned*)(clo + base0 + col) = ul;
        split2(acc_o[nf][2] * r1, acc_o[nf][3] * r1, uh, ul);
        *(unsigned*)(chi + base1 + col) = uh;
        *(unsigned*)(clo + base1 + col) = ul;
    }
}

// ---------------------------------------------------------------------------
extern "C" void kernel_launch(void* const* d_in, const int* in_sizes, int n_in,
                              void* d_out, int out_size)
{
    const float* x     = (const float*)d_in[0];
    const float* w_qkv = (const float*)d_in[1];
    const float* w_out = (const float*)d_in[2];
    float* out = (float*)d_out;

    float* qkv_p;
    cudaGetSymbolAddress((void**)&qkv_p, g_qkv);

    __nv_bfloat16 *xhi, *xlo, *wqhi, *wqlo, *wohi, *wolo, *chi, *clo;
    cudaGetSymbolAddress((void**)&xhi,  g_xhi);
    cudaGetSymbolAddress((void**)&xlo,  g_xlo);
    cudaGetSymbolAddress((void**)&wqhi, g_wqhi);
    cudaGetSymbolAddress((void**)&wqlo, g_wqlo);
    cudaGetSymbolAddress((void**)&wohi, g_wohi);
    cudaGetSymbolAddress((void**)&wolo, g_wolo);
    cudaGetSymbolAddress((void**)&chi,  g_chi);
    cudaGetSymbolAddress((void**)&clo,  g_clo);

    // 0) bf16 hi/lo splits of x, w_qkv, w_out
    {
        int n4 = NTOK * K_ / 4;
        split_bf16<<<(n4 + 255) / 256, 256>>>(x, xhi, xlo, n4);
        n4 = MQKV * K_ / 4;
        split_bf16<<<(n4 + 255) / 256, 256>>>(w_qkv, wqhi, wqlo, n4);
        n4 = D_ * K_ / 4;
        split_bf16<<<(n4 + 255) / 256, 256>>>(w_out, wohi, wolo, n4);
    }

    // 1) QKV projection (tensor cores, bf16x3): [4096,1024] @ [3072,1024]^T
    gemm_bf16x3<<<dim3(MQKV / BN, NTOK / BM), 256>>>(xhi, xlo, wqhi, wqlo, qkv_p, MQKV);

    // 2) Fused flash attention (scores + ALiBi + causal softmax + P@V),
    //    writes ctx directly as bf16 hi/lo
    flash_kernel<<<dim3(T_ / 128, B_ * H_), 256>>>(qkv_p, chi, clo);

    // 3) Output projection (tensor cores, bf16x3)
    gemm_bf16x3<<<dim3(D_ / BN, NTOK / BM), 256>>>(chi, clo, wohi, wolo, out, D_);
}

// round 11
// speedup vs baseline: 1.6883x; 1.6883x over previous
#include <cuda_runtime.h>
#include <cuda_bf16.h>
#include <math_constants.h>

// Fixed problem shapes
#define B_ 2
#define T_ 2048
#define D_ 1024
#define H_ 16
#define HD_ 64
#define NTOK (B_ * T_)          // 4096
#define MQKV (3 * D_)           // 3072
#define K_ 1024

// Scratch (allocation-free rule: __device__ globals)
__device__ float g_qkv[NTOK * MQKV];                       // [4096, 3072] fp32 q|k|v

// bf16 hi/lo split scratch
__device__ __nv_bfloat16 g_xhi[NTOK * K_],  g_xlo[NTOK * K_];
__device__ __nv_bfloat16 g_wqhi[MQKV * K_], g_wqlo[MQKV * K_];
__device__ __nv_bfloat16 g_wohi[D_ * K_],   g_wolo[D_ * K_];
__device__ __nv_bfloat16 g_chi[NTOK * K_],  g_clo[NTOK * K_];   // ctx hi/lo (flash output)

// ---------------------------------------------------------------------------
// helpers
// ---------------------------------------------------------------------------
__device__ __forceinline__ void split2(float x, float y, unsigned &hi, unsigned &lo)
{
    __nv_bfloat16 hx = __float2bfloat16(x), hy = __float2bfloat16(y);
    __nv_bfloat162 h(hx, hy);
    __nv_bfloat162 l(__float2bfloat16(x - __bfloat162float(hx)),
                     __float2bfloat16(y - __bfloat162float(hy)));
    hi = *(unsigned*)&h;
    lo = *(unsigned*)&l;
}

__device__ __forceinline__ void mma16816(float c[4], const unsigned a[4], const unsigned b[2])
{
    asm volatile(
        "mma.sync.aligned.m16n8k16.row.col.f32.bf16.bf16.f32 "
        "{%0,%1,%2,%3}, {%4,%5,%6,%7}, {%8,%9}, {%0,%1,%2,%3};\n"
        : "+f"(c[0]), "+f"(c[1]), "+f"(c[2]), "+f"(c[3])
        : "r"(a[0]), "r"(a[1]), "r"(a[2]), "r"(a[3]), "r"(b[0]), "r"(b[1]));
}

__device__ __forceinline__ unsigned sptr(const void* p)
{
    return (unsigned)__cvta_generic_to_shared(p);
}

__device__ __forceinline__ void cpa16(unsigned saddr, const void* gaddr)
{
    asm volatile("cp.async.cg.shared.global [%0], [%1], 16;\n" :: "r"(saddr), "l"(gaddr));
}
__device__ __forceinline__ void cpa_commit()
{
    asm volatile("cp.async.commit_group;\n");
}
template <int N>
__device__ __forceinline__ void cpa_wait()
{
    asm volatile("cp.async.wait_group %0;\n" :: "n"(N));
}

// ---------------------------------------------------------------------------
// Split fp32 -> bf16 hi + bf16 lo (residual). Vectorized by 4.
// ---------------------------------------------------------------------------
__global__ __launch_bounds__(256) void split_bf16(
    const float* __restrict__ in, __nv_bfloat16* __restrict__ hi,
    __nv_bfloat16* __restrict__ lo, int n4)
{
    int i = blockIdx.x * 256 + threadIdx.x;
    if (i >= n4) return;
    float4 v = ((const float4*)in)[i];
    unsigned h0, l0, h1, l1;
    split2(v.x, v.y, h0, l0);
    split2(v.z, v.w, h1, l1);
    ((unsigned*)hi)[i * 2 + 0] = h0;
    ((unsigned*)hi)[i * 2 + 1] = h1;
    ((unsigned*)lo)[i * 2 + 0] = l0;
    ((unsigned*)lo)[i * 2 + 1] = l1;
}

// ---------------------------------------------------------------------------
// Tensor-core NT GEMM, bf16x3 split: C[N,M] = A[N,K] @ W[M,K]^T in ~fp32 prec.
// mma.sync.m16n8k16.bf16, scalar LDS fragment loads (proven faster than ldsm),
// cp.async 2-stage smem double buffer, 2 CTAs/SM.
// Block 128x128, BK=32, 8 warps, warp tile 64x32. Dynamic smem: 2 stages.
// ---------------------------------------------------------------------------
#define BM 128
#define BN 128
#define BK 32
#define SSTR 40                         // 80B row stride, conflict-free LDS
#define MATSZ (BM * SSTR)               // elements per matrix per stage (5120)
#define STAGESZ (4 * MATSZ)             // elements per stage (20480)
#define GEMM_SMEM (2 * STAGESZ * 2)     // bytes (81920)

__global__ __launch_bounds__(256, 2) void gemm_bf16x3(
    const __nv_bfloat16* __restrict__ Ahi, const __nv_bfloat16* __restrict__ Alo,
    const __nv_bfloat16* __restrict__ Whi, const __nv_bfloat16* __restrict__ Wlo,
    float* __restrict__ C, int Mcols)
{
    extern __shared__ __nv_bfloat16 dsm[];

    const int tid  = threadIdx.x;
    const int warp = tid >> 5;
    const int lane = tid & 31;
    const int wm = warp >> 2;
    const int wn = warp & 3;
    const int g  = lane >> 2;
    const int tg = lane & 3;
    const int rowBase = blockIdx.y * BM;
    const int colBase = blockIdx.x * BN;

    // per-thread fill coords (2 x 16B per matrix per stage)
    const int fr0 = tid >> 2;            // rows tid/4 and tid/4+64
    const int fc8 = (tid & 3) * 8;

    float acc[4][4][4];
#pragma unroll
    for (int im = 0; im < 4; im++)
#pragma unroll
        for (int in = 0; in < 4; in++)
#pragma unroll
            for (int q = 0; q < 4; q++) acc[im][in][q] = 0.f;

    // stage fill via cp.async
    auto fill = [&](int stage, int k0) {
        __nv_bfloat16* base = dsm + stage * STAGESZ;
#pragma unroll
        for (int l = 0; l < 2; l++) {
            int r = fr0 + l * 64;
            unsigned soff = (unsigned)(r * SSTR + fc8);
            size_t aoff = (size_t)(rowBase + r) * K_ + k0 + fc8;
            size_t boff = (size_t)(colBase + r) * K_ + k0 + fc8;
            cpa16(sptr(base + soff),              Ahi + aoff);
            cpa16(sptr(base + MATSZ + soff),      Alo + aoff);
            cpa16(sptr(base + 2 * MATSZ + soff),  Whi + boff);
            cpa16(sptr(base + 3 * MATSZ + soff),  Wlo + boff);
        }
        cpa_commit();
    };

    const int NK = K_ / BK;   // 32
    fill(0, 0);

    for (int kt = 0; kt < NK; kt++) {
        const int stage = kt & 1;
        if (kt + 1 < NK) {
            fill(stage ^ 1, (kt + 1) * BK);
            cpa_wait<1>();
        } else {
            cpa_wait<0>();
        }
        __syncthreads();

        const __nv_bfloat16* sAh = dsm + stage * STAGESZ;
        const __nv_bfloat16* sAl = sAh + MATSZ;
        const __nv_bfloat16* sBh = sAh + 2 * MATSZ;
        const __nv_bfloat16* sBl = sAh + 3 * MATSZ;

#pragma unroll
        for (int ks = 0; ks < BK; ks += 16) {
            unsigned ahi[4][4], alo[4][4], bhi[4][2], blo[4][2];
            const int c0 = ks + tg * 2;
#pragma unroll
            for (int im = 0; im < 4; im++) {
                int ra = wm * 64 + im * 16 + g;
                ahi[im][0] = *(const unsigned*)&sAh[ra * SSTR + c0];
                ahi[im][1] = *(const unsigned*)&sAh[(ra + 8) * SSTR + c0];
                ahi[im][2] = *(const unsigned*)&sAh[ra * SSTR + c0 + 8];
                ahi[im][3] = *(const unsigned*)&sAh[(ra + 8) * SSTR + c0 + 8];
                alo[im][0] = *(const unsigned*)&sAl[ra * SSTR + c0];
                alo[im][1] = *(const unsigned*)&sAl[(ra + 8) * SSTR + c0];
                alo[im][2] = *(const unsigned*)&sAl[ra * SSTR + c0 + 8];
                alo[im][3] = *(const unsigned*)&sAl[(ra + 8) * SSTR + c0 + 8];
            }
#pragma unroll
            for (int in = 0; in < 4; in++) {
                int nb = wn * 32 + in * 8 + g;
                bhi[in][0] = *(const unsigned*)&sBh[nb * SSTR + c0];
                bhi[in][1] = *(const unsigned*)&sBh[nb * SSTR + c0 + 8];
                blo[in][0] = *(const unsigned*)&sBl[nb * SSTR + c0];
                blo[in][1] = *(const unsigned*)&sBl[nb * SSTR + c0 + 8];
            }
#pragma unroll
            for (int im = 0; im < 4; im++)
#pragma unroll
                for (int in = 0; in < 4; in++) {
                    mma16816(acc[im][in], ahi[im], bhi[in]);
                    mma16816(acc[im][in], ahi[im], blo[in]);
                    mma16816(acc[im][in], alo[im], bhi[in]);
                }
        }
        __syncthreads();   // protect this stage's buffer before it is refilled
    }

#pragma unroll
    for (int im = 0; im < 4; im++) {
#pragma unroll
        for (int in = 0; in < 4; in++) {
            int row = rowBase + wm * 64 + im * 16 + g;
            int col = colBase + wn * 32 + in * 8 + tg * 2;
            float2 v01 = make_float2(acc[im][in][0], acc[im][in][1]);
            float2 v23 = make_float2(acc[im][in][2], acc[im][in][3]);
            *(float2*)(C + (size_t)row * Mcols + col)       = v01;
            *(float2*)(C + (size_t)(row + 8) * Mcols + col) = v23;
        }
    }
}

// ---------------------------------------------------------------------------
// Fused flash attention (R9-proven scalar-LDS form): scores (scale+ALiBi+causal)
// + online softmax + P@V. Block = 128 q-rows (8 warps x 16 rows), j-tiles of 64.
// ---------------------------------------------------------------------------
#define FSTR 72   // conflict-free scalar fragment loads

__global__ __launch_bounds__(256, 1) void flash_kernel(
    const float* __restrict__ qkv,
    __nv_bfloat16* __restrict__ chi, __nv_bfloat16* __restrict__ clo)
{
    __shared__ __nv_bfloat16 sKhi[64][FSTR], sKlo[64][FSTR];
    __shared__ __nv_bfloat16 sVhi[64][FSTR], sVlo[64][FSTR];   // transposed: [e][j]

    const int iblk = (int)gridDim.x - 1 - (int)blockIdx.x;  // big tiles first
    const int bh   = blockIdx.y;
    const int b    = bh >> 4;
    const int h    = bh & 15;
    const int tid  = threadIdx.x;
    const int warp = tid >> 5;
    const int lane = tid & 31;
    const int g    = lane >> 2;
    const int tg   = lane & 3;
    const int rbase = iblk * 128 + warp * 16;               // batch-local q-row base of warp
    const float slope = exp2f(-(float)(h + 1) / 16.f);

    const float* qkbase = qkv + (size_t)(b * T_) * MQKV + h * HD_;

    // Q fragments straight from gmem fp32 (once per block), hi/lo split
    unsigned qhi[4][4], qlo[4][4];
#pragma unroll
    for (int kb = 0; kb < 4; kb++)
#pragma unroll
        for (int r = 0; r < 4; r++) {
            int row = rbase + g + (r & 1) * 8;
            int col = kb * 16 + tg * 2 + (r >> 1) * 8;
            float2 v = *(const float2*)(qkbase + (size_t)row * MQKV + col);
            split2(v.x, v.y, qhi[kb][r], qlo[kb][r]);
        }

    float acc_o[8][4];
#pragma unroll
    for (int nf = 0; nf < 8; nf++)
#pragma unroll
        for (int q = 0; q < 4; q++) acc_o[nf][q] = 0.f;
    float m0 = -CUDART_INF_F, m1 = -CUDART_INF_F;
    float l0 = 0.f, l1 = 0.f;

    const int gi0 = rbase + g;
    const int gi1 = gi0 + 8;
    const int jt_max = (iblk * 128 + 127) >> 6;

    const int ldj  = tid >> 4;              // 0..15 base row (stride 16 over 4 its)
    const int lde4 = (tid & 15) * 4;        // element-4 column

    for (int jt = 0; jt <= jt_max; jt++) {
        // load K (row layout) and V (transposed) tiles, fp32 -> bf16 hi/lo
        const float* tilebase = qkbase + (size_t)(jt * 64) * MQKV;
#pragma unroll
        for (int it = 0; it < 4; it++) {
            int j = it * 16 + ldj;
            const float* src = tilebase + (size_t)j * MQKV;
            float4 kv = *(const float4*)(src + D_ + lde4);
            unsigned kh0, kl0, kh1, kl1;
            split2(kv.x, kv.y, kh0, kl0);
            split2(kv.z, kv.w, kh1, kl1);
            *(unsigned*)&sKhi[j][lde4]     = kh0;
            *(unsigned*)&sKhi[j][lde4 + 2] = kh1;
            *(unsigned*)&sKlo[j][lde4]     = kl0;
            *(unsigned*)&sKlo[j][lde4 + 2] = kl1;

            float4 vv = *(const float4*)(src + 2 * D_ + lde4);
            float vf[4] = {vv.x, vv.y, vv.z, vv.w};
#pragma unroll
            for (int q = 0; q < 4; q++) {
                __nv_bfloat16 hb = __float2bfloat16(vf[q]);
                sVhi[lde4 + q][j] = hb;
                sVlo[lde4 + q][j] = __float2bfloat16(vf[q] - __bfloat162float(hb));
            }
        }
        __syncthreads();

        if (jt * 64 <= rbase + 15) {
            // --- S = Q K^T (bf16x3) ---
            float s[8][4];
#pragma unroll
            for (int nf = 0; nf < 8; nf++)
#pragma unroll
                for (int q = 0; q < 4; q++) s[nf][q] = 0.f;

#pragma unroll
            for (int kb = 0; kb < 4; kb++) {
                const int c0 = kb * 16 + tg * 2;
#pragma unroll
                for (int nf = 0; nf < 8; nf++) {
                    unsigned kbh[2], kbl[2];
                    kbh[0] = *(const unsigned*)&sKhi[nf * 8 + g][c0];
                    kbh[1] = *(const unsigned*)&sKhi[nf * 8 + g][c0 + 8];
                    kbl[0] = *(const unsigned*)&sKlo[nf * 8 + g][c0];
                    kbl[1] = *(const unsigned*)&sKlo[nf * 8 + g][c0 + 8];
                    mma16816(s[nf], qhi[kb], kbh);
                    mma16816(s[nf], qlo[kb], kbh);
                    mma16816(s[nf], qhi[kb], kbl);
                }
            }

            // --- scale + ALiBi + causal mask ---
#pragma unroll
            for (int nf = 0; nf < 8; nf++) {
                int j0 = jt * 64 + nf * 8 + tg * 2;
                s[nf][0] = (j0     <= gi0) ? s[nf][0] * 0.125f + slope * (float)(j0     - gi0) : -CUDART_INF_F;
                s[nf][1] = (j0 + 1 <= gi0) ? s[nf][1] * 0.125f + slope * (float)(j0 + 1 - gi0) : -CUDART_INF_F;
                s[nf][2] = (j0     <= gi1) ? s[nf][2] * 0.125f + slope * (float)(j0     - gi1) : -CUDART_INF_F;
                s[nf][3] = (j0 + 1 <= gi1) ? s[nf][3] * 0.125f + slope * (float)(j0 + 1 - gi1) : -CUDART_INF_F;
            }

            // --- online softmax update ---
            float tm0 = -CUDART_INF_F, tm1 = -CUDART_INF_F;
#pragma unroll
            for (int nf = 0; nf < 8; nf++) {
                tm0 = fmaxf(tm0, fmaxf(s[nf][0], s[nf][1]));
                tm1 = fmaxf(tm1, fmaxf(s[nf][2], s[nf][3]));
            }
            tm0 = fmaxf(tm0, __shfl_xor_sync(0xffffffffu, tm0, 1));
            tm0 = fmaxf(tm0, __shfl_xor_sync(0xffffffffu, tm0, 2));
            tm1 = fmaxf(tm1, __shfl_xor_sync(0xffffffffu, tm1, 1));
            tm1 = fmaxf(tm1, __shfl_xor_sync(0xffffffffu, tm1, 2));
            float mn0 = fmaxf(m0, tm0), mn1 = fmaxf(m1, tm1);
            float a0 = __expf(m0 - mn0), a1 = __expf(m1 - mn1);

            float sum0 = 0.f, sum1 = 0.f;
#pragma unroll
            for (int nf = 0; nf < 8; nf++) {
                s[nf][0] = __expf(s[nf][0] - mn0);
                s[nf][1] = __expf(s[nf][1] - mn0);
                s[nf][2] = __expf(s[nf][2] - mn1);
                s[nf][3] = __expf(s[nf][3] - mn1);
                sum0 += s[nf][0] + s[nf][1];
                sum1 += s[nf][2] + s[nf][3];
            }
            sum0 += __shfl_xor_sync(0xffffffffu, sum0, 1);
            sum0 += __shfl_xor_sync(0xffffffffu, sum0, 2);
            sum1 += __shfl_xor_sync(0xffffffffu, sum1, 1);
            sum1 += __shfl_xor_sync(0xffffffffu, sum1, 2);
            l0 = l0 * a0 + sum0;
            l1 = l1 * a1 + sum1;
            m0 = mn0; m1 = mn1;

#pragma unroll
            for (int nf = 0; nf < 8; nf++) {
                acc_o[nf][0] *= a0; acc_o[nf][1] *= a0;
                acc_o[nf][2] *= a1; acc_o[nf][3] *= a1;
            }

            // --- O += P @ V : S-accum frags feed A operand directly ---
#pragma unroll
            for (int kb = 0; kb < 4; kb++) {
                unsigned pah[4], pal[4];
                split2(s[2 * kb][0],     s[2 * kb][1],     pah[0], pal[0]);
                split2(s[2 * kb][2],     s[2 * kb][3],     pah[1], pal[1]);
                split2(s[2 * kb + 1][0], s[2 * kb + 1][1], pah[2], pal[2]);
                split2(s[2 * kb + 1][2], s[2 * kb + 1][3], pah[3], pal[3]);
                const int c0 = kb * 16 + tg * 2;
#pragma unroll
                for (int nf = 0; nf < 8; nf++) {
                    unsigned vbh[2], vbl[2];
                    vbh[0] = *(const unsigned*)&sVhi[nf * 8 + g][c0];
                    vbh[1] = *(const unsigned*)&sVhi[nf * 8 + g][c0 + 8];
                    vbl[0] = *(const unsigned*)&sVlo[nf * 8 + g][c0];
                    vbl[1] = *(const unsigned*)&sVlo[nf * 8 + g][c0 + 8];
                    mma16816(acc_o[nf], pah, vbh);
                    mma16816(acc_o[nf], pal, vbh);
                    mma16816(acc_o[nf], pah, vbl);
                }
            }
        }
        __syncthreads();
    }

    // --- epilogue: O /= l, write ctx as bf16 hi/lo ---
    const float r0 = 1.f / l0, r1 = 1.f / l1;
    const size_t base0 = (size_t)(b * T_ + gi0) * D_ + h * HD_;
    const size_t base1 = base0 + (size_t)8 * D_;
#pragma unroll
    for (int nf = 0; nf < 8; nf++) {
        int col = nf * 8 + tg * 2;
        unsigned uh, ul;
        split2(acc_o[nf][0] * r0, acc_o[nf][1] * r0, uh, ul);
        *(unsigned*)(chi + base0 + col) = uh;
        *(unsigned*)(clo + base0 + col) = ul;
        split2(acc_o[nf][2] * r1, acc_o[nf][3] * r1, uh, ul);
        *(unsigned*)(chi + base1 + col) = uh;
        *(unsigned*)(clo + base1 + col) = ul;
    }
}

// ---------------------------------------------------------------------------
extern "C" void kernel_launch(void* const* d_in, const int* in_sizes, int n_in,
                              void* d_out, int out_size)
{
    const float* x     = (const float*)d_in[0];
    const float* w_qkv = (const float*)d_in[1];
    const float* w_out = (const float*)d_in[2];
    float* out = (float*)d_out;

    float* qkv_p;
    cudaGetSymbolAddress((void**)&qkv_p, g_qkv);

    __nv_bfloat16 *xhi, *xlo, *wqhi, *wqlo, *wohi, *wolo, *chi, *clo;
    cudaGetSymbolAddress((void**)&xhi,  g_xhi);
    cudaGetSymbolAddress((void**)&xlo,  g_xlo);
    cudaGetSymbolAddress((void**)&wqhi, g_wqhi);
    cudaGetSymbolAddress((void**)&wqlo, g_wqlo);
    cudaGetSymbolAddress((void**)&wohi, g_wohi);
    cudaGetSymbolAddress((void**)&wolo, g_wolo);
    cudaGetSymbolAddress((void**)&chi,  g_chi);
    cudaGetSymbolAddress((void**)&clo,  g_clo);

    // allow 80KB dynamic smem for the double-buffered GEMM (host-side attr,
    // not a stream op -> graph-capture safe; idempotent)
    cudaFuncSetAttribute(gemm_bf16x3, cudaFuncAttributeMaxDynamicSharedMemorySize, GEMM_SMEM);

    // 0) bf16 hi/lo splits of x, w_qkv, w_out
    {
        int n4 = NTOK * K_ / 4;
        split_bf16<<<(n4 + 255) / 256, 256>>>(x, xhi, xlo, n4);
        n4 = MQKV * K_ / 4;
        split_bf16<<<(n4 + 255) / 256, 256>>>(w_qkv, wqhi, wqlo, n4);
        n4 = D_ * K_ / 4;
        split_bf16<<<(n4 + 255) / 256, 256>>>(w_out, wohi, wolo, n4);
    }

    // 1) QKV projection (tensor cores, bf16x3): [4096,1024] @ [3072,1024]^T
    gemm_bf16x3<<<dim3(MQKV / BN, NTOK / BM), 256, GEMM_SMEM>>>(xhi, xlo, wqhi, wqlo, qkv_p, MQKV);

    // 2) Fused flash attention (scores + ALiBi + causal softmax + P@V),
    //    writes ctx directly as bf16 hi/lo
    flash_kernel<<<dim3(T_ / 128, B_ * H_), 256>>>(qkv_p, chi, clo);

    // 3) Output projection (tensor cores, bf16x3)
    gemm_bf16x3<<<dim3(D_ / BN, NTOK / BM), 256, GEMM_SMEM>>>(chi, clo, wohi, wolo, out, D_);
}

// round 13
// speedup vs baseline: 1.8889x; 1.1189x over previous
#include <cuda_runtime.h>
#include <cuda_bf16.h>
#include <math_constants.h>

// Fixed problem shapes
#define B_ 2
#define T_ 2048
#define D_ 1024
#define H_ 16
#define HD_ 64
#define NTOK (B_ * T_)          // 4096
#define MQKV (3 * D_)           // 3072
#define K_ 1024

// Scratch (allocation-free rule: __device__ globals)
__device__ float g_qkv[NTOK * MQKV];                       // [4096, 3072] fp32 q|k|v

// bf16 hi/lo split scratch
__device__ __nv_bfloat16 g_xhi[NTOK * K_],  g_xlo[NTOK * K_];
__device__ __nv_bfloat16 g_wqhi[MQKV * K_], g_wqlo[MQKV * K_];
__device__ __nv_bfloat16 g_wohi[D_ * K_],   g_wolo[D_ * K_];
__device__ __nv_bfloat16 g_chi[NTOK * K_],  g_clo[NTOK * K_];   // ctx hi/lo (flash output)

// pre-split K (row-major per bh) and V (transposed per bh) for flash
#define KVSZ (B_ * H_ * T_ * HD_)    // 4.19M
__device__ __nv_bfloat16 g_khi[KVSZ],  g_klo[KVSZ];    // [bh][t][e]
__device__ __nv_bfloat16 g_vthi[KVSZ], g_vtlo[KVSZ];   // [bh][e][t]

// ---------------------------------------------------------------------------
// helpers
// ---------------------------------------------------------------------------
__device__ __forceinline__ void split2(float x, float y, unsigned &hi, unsigned &lo)
{
    __nv_bfloat16 hx = __float2bfloat16(x), hy = __float2bfloat16(y);
    __nv_bfloat162 h(hx, hy);
    __nv_bfloat162 l(__float2bfloat16(x - __bfloat162float(hx)),
                     __float2bfloat16(y - __bfloat162float(hy)));
    hi = *(unsigned*)&h;
    lo = *(unsigned*)&l;
}

__device__ __forceinline__ void mma16816(float c[4], const unsigned a[4], const unsigned b[2])
{
    asm volatile(
        "mma.sync.aligned.m16n8k16.row.col.f32.bf16.bf16.f32 "
        "{%0,%1,%2,%3}, {%4,%5,%6,%7}, {%8,%9}, {%0,%1,%2,%3};\n"
        : "+f"(c[0]), "+f"(c[1]), "+f"(c[2]), "+f"(c[3])
        : "r"(a[0]), "r"(a[1]), "r"(a[2]), "r"(a[3]), "r"(b[0]), "r"(b[1]));
}

__device__ __forceinline__ unsigned sptr(const void* p)
{
    return (unsigned)__cvta_generic_to_shared(p);
}

__device__ __forceinline__ void cpa16(unsigned saddr, const void* gaddr)
{
    asm volatile("cp.async.cg.shared.global [%0], [%1], 16;\n" :: "r"(saddr), "l"(gaddr));
}
__device__ __forceinline__ void cpa_commit()
{
    asm volatile("cp.async.commit_group;\n");
}
template <int N>
__device__ __forceinline__ void cpa_wait()
{
    asm volatile("cp.async.wait_group %0;\n" :: "n"(N));
}

// ---------------------------------------------------------------------------
// Split fp32 -> bf16 hi + bf16 lo (residual). Vectorized by 4.
// ---------------------------------------------------------------------------
__global__ __launch_bounds__(256) void split_bf16(
    const float* __restrict__ in, __nv_bfloat16* __restrict__ hi,
    __nv_bfloat16* __restrict__ lo, int n4)
{
    int i = blockIdx.x * 256 + threadIdx.x;
    if (i >= n4) return;
    float4 v = ((const float4*)in)[i];
    unsigned h0, l0, h1, l1;
    split2(v.x, v.y, h0, l0);
    split2(v.z, v.w, h1, l1);
    ((unsigned*)hi)[i * 2 + 0] = h0;
    ((unsigned*)hi)[i * 2 + 1] = h1;
    ((unsigned*)lo)[i * 2 + 0] = l0;
    ((unsigned*)lo)[i * 2 + 1] = l1;
}

// ---------------------------------------------------------------------------
// kv_split: pre-split K (per-bh row major) and V (per-bh TRANSPOSED) to bf16
// hi/lo so the flash kernel can cp.async them with zero conversion work.
// grid (T/64, B*H), block 256.
// ---------------------------------------------------------------------------
__global__ __launch_bounds__(256) void kv_split(
    const float* __restrict__ qkv,
    __nv_bfloat16* __restrict__ khi,  __nv_bfloat16* __restrict__ klo,
    __nv_bfloat16* __restrict__ vthi, __nv_bfloat16* __restrict__ vtlo)
{
    const int jt = blockIdx.x;
    const int bh = blockIdx.y;
    const int b  = bh >> 4;
    const int h  = bh & 15;
    const int tid = threadIdx.x;

    __shared__ float sv[64][65];

    const float* base = qkv + (size_t)(b * T_ + jt * 64) * MQKV + h * HD_;

    // K: direct split, coalesced both sides; stage V tile into smem
    for (int idx = tid; idx < 64 * 64; idx += 256) {
        int r = idx >> 6, e = idx & 63;
        float kx = base[(size_t)r * MQKV + D_ + e];
        __nv_bfloat16 hb = __float2bfloat16(kx);
        size_t o = (size_t)(bh * T_ + jt * 64 + r) * HD_ + e;
        khi[o] = hb;
        klo[o] = __float2bfloat16(kx - __bfloat162float(hb));
        sv[r][e] = base[(size_t)r * MQKV + 2 * D_ + e];
    }
    __syncthreads();

    // V: transposed split, coalesced writes along t
    for (int idx = tid; idx < 64 * 64; idx += 256) {
        int e = idx >> 6, j = idx & 63;
        float vx = sv[j][e];
        __nv_bfloat16 hb = __float2bfloat16(vx);
        size_t o = ((size_t)bh * HD_ + e) * T_ + jt * 64 + j;
        vthi[o] = hb;
        vtlo[o] = __float2bfloat16(vx - __bfloat162float(hb));
    }
}

// ---------------------------------------------------------------------------
// Tensor-core NT GEMM, bf16x3 split (R11-proven): cp.async 2-stage, 2 CTA/SM.
// ---------------------------------------------------------------------------
#define BM 128
#define BN 128
#define BK 32
#define SSTR 40                         // 80B row stride, conflict-free LDS
#define MATSZ (BM * SSTR)
#define STAGESZ (4 * MATSZ)
#define GEMM_SMEM (2 * STAGESZ * 2)

__global__ __launch_bounds__(256, 2) void gemm_bf16x3(
    const __nv_bfloat16* __restrict__ Ahi, const __nv_bfloat16* __restrict__ Alo,
    const __nv_bfloat16* __restrict__ Whi, const __nv_bfloat16* __restrict__ Wlo,
    float* __restrict__ C, int Mcols)
{
    extern __shared__ __nv_bfloat16 dsm[];

    const int tid  = threadIdx.x;
    const int warp = tid >> 5;
    const int lane = tid & 31;
    const int wm = warp >> 2;
    const int wn = warp & 3;
    const int g  = lane >> 2;
    const int tg = lane & 3;
    const int rowBase = blockIdx.y * BM;
    const int colBase = blockIdx.x * BN;

    const int fr0 = tid >> 2;
    const int fc8 = (tid & 3) * 8;

    float acc[4][4][4];
#pragma unroll
    for (int im = 0; im < 4; im++)
#pragma unroll
        for (int in = 0; in < 4; in++)
#pragma unroll
            for (int q = 0; q < 4; q++) acc[im][in][q] = 0.f;

    auto fill = [&](int stage, int k0) {
        __nv_bfloat16* base = dsm + stage * STAGESZ;
#pragma unroll
        for (int l = 0; l < 2; l++) {
            int r = fr0 + l * 64;
            unsigned soff = (unsigned)(r * SSTR + fc8);
            size_t aoff = (size_t)(rowBase + r) * K_ + k0 + fc8;
            size_t boff = (size_t)(colBase + r) * K_ + k0 + fc8;
            cpa16(sptr(base + soff),              Ahi + aoff);
            cpa16(sptr(base + MATSZ + soff),      Alo + aoff);
            cpa16(sptr(base + 2 * MATSZ + soff),  Whi + boff);
            cpa16(sptr(base + 3 * MATSZ + soff),  Wlo + boff);
        }
        cpa_commit();
    };

    const int NK = K_ / BK;
    fill(0, 0);

    for (int kt = 0; kt < NK; kt++) {
        const int stage = kt & 1;
        if (kt + 1 < NK) {
            fill(stage ^ 1, (kt + 1) * BK);
            cpa_wait<1>();
        } else {
            cpa_wait<0>();
        }
        __syncthreads();

        const __nv_bfloat16* sAh = dsm + stage * STAGESZ;
        const __nv_bfloat16* sAl = sAh + MATSZ;
        const __nv_bfloat16* sBh = sAh + 2 * MATSZ;
        const __nv_bfloat16* sBl = sAh + 3 * MATSZ;

#pragma unroll
        for (int ks = 0; ks < BK; ks += 16) {
            unsigned ahi[4][4], alo[4][4], bhi[4][2], blo[4][2];
            const int c0 = ks + tg * 2;
#pragma unroll
            for (int im = 0; im < 4; im++) {
                int ra = wm * 64 + im * 16 + g;
                ahi[im][0] = *(const unsigned*)&sAh[ra * SSTR + c0];
                ahi[im][1] = *(const unsigned*)&sAh[(ra + 8) * SSTR + c0];
                ahi[im][2] = *(const unsigned*)&sAh[ra * SSTR + c0 + 8];
                ahi[im][3] = *(const unsigned*)&sAh[(ra + 8) * SSTR + c0 + 8];
                alo[im][0] = *(const unsigned*)&sAl[ra * SSTR + c0];
                alo[im][1] = *(const unsigned*)&sAl[(ra + 8) * SSTR + c0];
                alo[im][2] = *(const unsigned*)&sAl[ra * SSTR + c0 + 8];
                alo[im][3] = *(const unsigned*)&sAl[(ra + 8) * SSTR + c0 + 8];
            }
#pragma unroll
            for (int in = 0; in < 4; in++) {
                int nb = wn * 32 + in * 8 + g;
                bhi[in][0] = *(const unsigned*)&sBh[nb * SSTR + c0];
                bhi[in][1] = *(const unsigned*)&sBh[nb * SSTR + c0 + 8];
                blo[in][0] = *(const unsigned*)&sBl[nb * SSTR + c0];
                blo[in][1] = *(const unsigned*)&sBl[nb * SSTR + c0 + 8];
            }
#pragma unroll
            for (int im = 0; im < 4; im++)
#pragma unroll
                for (int in = 0; in < 4; in++) {
                    mma16816(acc[im][in], ahi[im], bhi[in]);
                    mma16816(acc[im][in], ahi[im], blo[in]);
                    mma16816(acc[im][in], alo[im], bhi[in]);
                }
        }
        __syncthreads();
    }

#pragma unroll
    for (int im = 0; im < 4; im++) {
#pragma unroll
        for (int in = 0; in < 4; in++) {
            int row = rowBase + wm * 64 + im * 16 + g;
            int col = colBase + wn * 32 + in * 8 + tg * 2;
            float2 v01 = make_float2(acc[im][in][0], acc[im][in][1]);
            float2 v23 = make_float2(acc[im][in][2], acc[im][in][3]);
            *(float2*)(C + (size_t)row * Mcols + col)       = v01;
            *(float2*)(C + (size_t)(row + 8) * Mcols + col) = v23;
        }
    }
}

// ---------------------------------------------------------------------------
// Fused flash attention with pre-split K/V and cp.async double buffering.
// Block = 128 q-rows (8 warps x 16 rows), j-tiles of 64.
// ---------------------------------------------------------------------------
#define FSTR 72                          // conflict-free scalar fragment loads
#define FMAT (64 * FSTR)                 // 4608 elements
#define FSTAGE (4 * FMAT)                // Khi,Klo,Vthi,Vtlo
#define FLASH_SMEM (2 * FSTAGE * 2)      // 73728 bytes

__global__ __launch_bounds__(256, 1) void flash_kernel(
    const float* __restrict__ qkv,
    const __nv_bfloat16* __restrict__ khi,  const __nv_bfloat16* __restrict__ klo,
    const __nv_bfloat16* __restrict__ vthi, const __nv_bfloat16* __restrict__ vtlo,
    __nv_bfloat16* __restrict__ chi, __nv_bfloat16* __restrict__ clo)
{
    extern __shared__ __nv_bfloat16 fsm[];

    const int iblk = (int)gridDim.x - 1 - (int)blockIdx.x;  // big tiles first
    const int bh   = blockIdx.y;
    const int b    = bh >> 4;
    const int h    = bh & 15;
    const int tid  = threadIdx.x;
    const int warp = tid >> 5;
    const int lane = tid & 31;
    const int g    = lane >> 2;
    const int tg   = lane & 3;
    const int rbase = iblk * 128 + warp * 16;               // batch-local q-row base
    const float slope = exp2f(-(float)(h + 1) / 16.f);

    const float* qkbase = qkv + (size_t)(b * T_) * MQKV + h * HD_;
    const __nv_bfloat16* khb = khi  + (size_t)bh * T_ * HD_;
    const __nv_bfloat16* klb = klo  + (size_t)bh * T_ * HD_;
    const __nv_bfloat16* vhb = vthi + (size_t)bh * HD_ * T_;
    const __nv_bfloat16* vlb = vtlo + (size_t)bh * HD_ * T_;

    // Q fragments straight from gmem fp32 (once per block), hi/lo split
    unsigned qhi[4][4], qlo[4][4];
#pragma unroll
    for (int kb = 0; kb < 4; kb++)
#pragma unroll
        for (int r = 0; r < 4; r++) {
            int row = rbase + g + (r & 1) * 8;
            int col = kb * 16 + tg * 2 + (r >> 1) * 8;
            float2 v = *(const float2*)(qkbase + (size_t)row * MQKV + col);
            split2(v.x, v.y, qhi[kb][r], qlo[kb][r]);
        }

    float acc_o[8][4];
#pragma unroll
    for (int nf = 0; nf < 8; nf++)
#pragma unroll
        for (int q = 0; q < 4; q++) acc_o[nf][q] = 0.f;
    float m0 = -CUDART_INF_F, m1 = -CUDART_INF_F;
    float l0 = 0.f, l1 = 0.f;

    const int gi0 = rbase + g;
    const int gi1 = gi0 + 8;
    const int jt_max = (iblk * 128 + 127) >> 6;

    // cp.async tile fill: 4 matrices x 64 rows x 8 chunks(16B) each,
    // 256 threads -> 2 chunk-ids each covering all 4 matrices
    auto fill = [&](int stage, int jt) {
        __nv_bfloat16* base = fsm + stage * FSTAGE;
        const __nv_bfloat16* kh = khb + (size_t)(jt * 64) * HD_;
        const __nv_bfloat16* kl = klb + (size_t)(jt * 64) * HD_;
        const __nv_bfloat16* vh = vhb + jt * 64;
        const __nv_bfloat16* vl = vlb + jt * 64;
#pragma unroll
        for (int l = 0; l < 2; l++) {
            int id = l * 256 + tid;          // 0..511
            int r  = id >> 3;                // 0..63
            int c8 = (id & 7) * 8;           // 0..56
            unsigned soff = (unsigned)(r * FSTR + c8);
            cpa16(sptr(base + soff),            kh + r * HD_ + c8);
            cpa16(sptr(base + FMAT + soff),     kl + r * HD_ + c8);
            cpa16(sptr(base + 2 * FMAT + soff), vh + (size_t)r * T_ + c8);
            cpa16(sptr(base + 3 * FMAT + soff), vl + (size_t)r * T_ + c8);
        }
        cpa_commit();
    };

    fill(0, 0);

    for (int jt = 0; jt <= jt_max; jt++) {
        const int stage = jt & 1;
        if (jt + 1 <= jt_max) {
            fill(stage ^ 1, jt + 1);
            cpa_wait<1>();
        } else {
            cpa_wait<0>();
        }
        __syncthreads();

        const __nv_bfloat16* sKh = fsm + stage * FSTAGE;
        const __nv_bfloat16* sKl = sKh + FMAT;
        const __nv_bfloat16* sVh = sKh + 2 * FMAT;
        const __nv_bfloat16* sVl = sKh + 3 * FMAT;

        if (jt * 64 <= rbase + 15) {
            // --- S = Q K^T (bf16x3) ---
            float s[8][4];
#pragma unroll
            for (int nf = 0; nf < 8; nf++)
#pragma unroll
                for (int q = 0; q < 4; q++) s[nf][q] = 0.f;

#pragma unroll
            for (int kb = 0; kb < 4; kb++) {
                const int c0 = kb * 16 + tg * 2;
#pragma unroll
                for (int nf = 0; nf < 8; nf++) {
                    const int rj = nf * 8 + g;
                    unsigned kbh[2], kbl[2];
                    kbh[0] = *(const unsigned*)&sKh[rj * FSTR + c0];
                    kbh[1] = *(const unsigned*)&sKh[rj * FSTR + c0 + 8];
                    kbl[0] = *(const unsigned*)&sKl[rj * FSTR + c0];
                    kbl[1] = *(const unsigned*)&sKl[rj * FSTR + c0 + 8];
                    mma16816(s[nf], qhi[kb], kbh);
                    mma16816(s[nf], qlo[kb], kbh);
                    mma16816(s[nf], qhi[kb], kbl);
                }
            }

            // --- scale + ALiBi + causal mask ---
#pragma unroll
            for (int nf = 0; nf < 8; nf++) {
                int j0 = jt * 64 + nf * 8 + tg * 2;
                s[nf][0] = (j0     <= gi0) ? s[nf][0] * 0.125f + slope * (float)(j0     - gi0) : -CUDART_INF_F;
                s[nf][1] = (j0 + 1 <= gi0) ? s[nf][1] * 0.125f + slope * (float)(j0 + 1 - gi0) : -CUDART_INF_F;
                s[nf][2] = (j0     <= gi1) ? s[nf][2] * 0.125f + slope * (float)(j0     - gi1) : -CUDART_INF_F;
                s[nf][3] = (j0 + 1 <= gi1) ? s[nf][3] * 0.125f + slope * (float)(j0 + 1 - gi1) : -CUDART_INF_F;
            }

            // --- online softmax update ---
            float tm0 = -CUDART_INF_F, tm1 = -CUDART_INF_F;
#pragma unroll
            for (int nf = 0; nf < 8; nf++) {
                tm0 = fmaxf(tm0, fmaxf(s[nf][0], s[nf][1]));
                tm1 = fmaxf(tm1, fmaxf(s[nf][2], s[nf][3]));
            }
            tm0 = fmaxf(tm0, __shfl_xor_sync(0xffffffffu, tm0, 1));
            tm0 = fmaxf(tm0, __shfl_xor_sync(0xffffffffu, tm0, 2));
            tm1 = fmaxf(tm1, __shfl_xor_sync(0xffffffffu, tm1, 1));
            tm1 = fmaxf(tm1, __shfl_xor_sync(0xffffffffu, tm1, 2));
            float mn0 = fmaxf(m0, tm0), mn1 = fmaxf(m1, tm1);
            float a0 = __expf(m0 - mn0), a1 = __expf(m1 - mn1);

            float sum0 = 0.f, sum1 = 0.f;
#pragma unroll
            for (int nf = 0; nf < 8; nf++) {
                s[nf][0] = __expf(s[nf][0] - mn0);
                s[nf][1] = __expf(s[nf][1] - mn0);
                s[nf][2] = __expf(s[nf][2] - mn1);
                s[nf][3] = __expf(s[nf][3] - mn1);
                sum0 += s[nf][0] + s[nf][1];
                sum1 += s[nf][2] + s[nf][3];
            }
            sum0 += __shfl_xor_sync(0xffffffffu, sum0, 1);
            sum0 += __shfl_xor_sync(0xffffffffu, sum0, 2);
            sum1 += __shfl_xor_sync(0xffffffffu, sum1, 1);
            sum1 += __shfl_xor_sync(0xffffffffu, sum1, 2);
            l0 = l0 * a0 + sum0;
            l1 = l1 * a1 + sum1;
            m0 = mn0; m1 = mn1;

#pragma unroll
            for (int nf = 0; nf < 8; nf++) {
                acc_o[nf][0] *= a0; acc_o[nf][1] *= a0;
                acc_o[nf][2] *= a1; acc_o[nf][3] *= a1;
            }

            // --- O += P @ V : S-accum frags feed A operand directly ---
#pragma unroll
            for (int kb = 0; kb < 4; kb++) {
                unsigned pah[4], pal[4];
                split2(s[2 * kb][0],     s[2 * kb][1],     pah[0], pal[0]);
                split2(s[2 * kb][2],     s[2 * kb][3],     pah[1], pal[1]);
                split2(s[2 * kb + 1][0], s[2 * kb + 1][1], pah[2], pal[2]);
                split2(s[2 * kb + 1][2], s[2 * kb + 1][3], pah[3], pal[3]);
                const int c0 = kb * 16 + tg * 2;
#pragma unroll
                for (int nf = 0; nf < 8; nf++) {
                    const int re = nf * 8 + g;
                    unsigned vbh[2], vbl[2];
                    vbh[0] = *(const unsigned*)&sVh[re * FSTR + c0];
                    vbh[1] = *(const unsigned*)&sVh[re * FSTR + c0 + 8];
                    vbl[0] = *(const unsigned*)&sVl[re * FSTR + c0];
                    vbl[1] = *(const unsigned*)&sVl[re * FSTR + c0 + 8];
                    mma16816(acc_o[nf], pah, vbh);
                    mma16816(acc_o[nf], pal, vbh);
                    mma16816(acc_o[nf], pah, vbl);
                }
            }
        }
        __syncthreads();
    }

    // --- epilogue: O /= l, write ctx as bf16 hi/lo ---
    const float r0 = 1.f / l0, r1 = 1.f / l1;
    const size_t base0 = (size_t)(b * T_ + gi0) * D_ + h * HD_;
    const size_t base1 = base0 + (size_t)8 * D_;
#pragma unroll
    for (int nf = 0; nf < 8; nf++) {
        int col = nf * 8 + tg * 2;
        unsigned uh, ul;
        split2(acc_o[nf][0] * r0, acc_o[nf][1] * r0, uh, ul);
        *(unsigned*)(chi + base0 + col) = uh;
        *(unsigned*)(clo + base0 + col) = ul;
        split2(acc_o[nf][2] * r1, acc_o[nf][3] * r1, uh, ul);
        *(unsigned*)(chi + base1 + col) = uh;
        *(unsigned*)(clo + base1 + col) = ul;
    }
}

// ---------------------------------------------------------------------------
extern "C" void kernel_launch(void* const* d_in, const int* in_sizes, int n_in,
                              void* d_out, int out_size)
{
    const float* x     = (const float*)d_in[0];
    const float* w_qkv = (const float*)d_in[1];
    const float* w_out = (const float*)d_in[2];
    float* out = (float*)d_out;

    float* qkv_p;
    cudaGetSymbolAddress((void**)&qkv_p, g_qkv);

    __nv_bfloat16 *xhi, *xlo, *wqhi, *wqlo, *wohi, *wolo, *chi, *clo;
    __nv_bfloat16 *khi, *klo, *vthi, *vtlo;
    cudaGetSymbolAddress((void**)&xhi,  g_xhi);
    cudaGetSymbolAddress((void**)&xlo,  g_xlo);
    cudaGetSymbolAddress((void**)&wqhi, g_wqhi);
    cudaGetSymbolAddress((void**)&wqlo, g_wqlo);
    cudaGetSymbolAddress((void**)&wohi, g_wohi);
    cudaGetSymbolAddress((void**)&wolo, g_wolo);
    cudaGetSymbolAddress((void**)&chi,  g_chi);
    cudaGetSymbolAddress((void**)&clo,  g_clo);
    cudaGetSymbolAddress((void**)&khi,  g_khi);
    cudaGetSymbolAddress((void**)&klo,  g_klo);
    cudaGetSymbolAddress((void**)&vthi, g_vthi);
    cudaGetSymbolAddress((void**)&vtlo, g_vtlo);

    // opt-in smem sizes (host-side attrs, graph-capture safe; idempotent)
    cudaFuncSetAttribute(gemm_bf16x3,  cudaFuncAttributeMaxDynamicSharedMemorySize, GEMM_SMEM);
    cudaFuncSetAttribute(flash_kernel, cudaFuncAttributeMaxDynamicSharedMemorySize, FLASH_SMEM);

    // 0) bf16 hi/lo splits of x, w_qkv, w_out
    {
        int n4 = NTOK * K_ / 4;
        split_bf16<<<(n4 + 255) / 256, 256>>>(x, xhi, xlo, n4);
        n4 = MQKV * K_ / 4;
        split_bf16<<<(n4 + 255) / 256, 256>>>(w_qkv, wqhi, wqlo, n4);
        n4 = D_ * K_ / 4;
        split_bf16<<<(n4 + 255) / 256, 256>>>(w_out, wohi, wolo, n4);
    }

    // 1) QKV projection (tensor cores, bf16x3)
    gemm_bf16x3<<<dim3(MQKV / BN, NTOK / BM), 256, GEMM_SMEM>>>(xhi, xlo, wqhi, wqlo, qkv_p, MQKV);

    // 1b) pre-split K (row major) and V (transposed) to bf16 hi/lo
    kv_split<<<dim3(T_ / 64, B_ * H_), 256>>>(qkv_p, khi, klo, vthi, vtlo);

    // 2) Fused flash attention (cp.async double-buffered K/V tiles)
    flash_kernel<<<dim3(T_ / 128, B_ * H_), 256, FLASH_SMEM>>>(
        qkv_p, khi, klo, vthi, vtlo, chi, clo);

    // 3) Output projection (tensor cores, bf16x3)
    gemm_bf16x3<<<dim3(D_ / BN, NTOK / BM), 256, GEMM_SMEM>>>(chi, clo, wohi, wolo, out, D_);
}

// round 15
// speedup vs baseline: 2.6135x; 1.3835x over previous
#include <cuda_runtime.h>
#include <cuda_fp16.h>
#include <math_constants.h>
#include <cstdint>

// Fixed problem shapes
#define B_ 2
#define T_ 2048
#define D_ 1024
#define H_ 16
#define HD_ 64
#define NTOK (B_ * T_)          // 4096
#define MQKV (3 * D_)           // 3072
#define K_ 1024

// Scratch (allocation-free rule: __device__ globals)
__device__ float g_qkv[NTOK * MQKV];                       // [4096, 3072] fp32 q|k|v

// fp16 split/rounded scratch
__device__ __half g_xhi[NTOK * K_],  g_xlo[NTOK * K_];     // x split (A of qkv gemm)
__device__ __half g_wqh[MQKV * K_];                        // w_qkv rounded (B)
__device__ __half g_woh[D_ * K_];                          // w_out rounded (B)
__device__ __half g_chi[NTOK * K_], g_clo[NTOK * K_];      // ctx split (A of out gemm)

// pre-rounded K (row-major per bh) and V (transposed per bh) for flash
#define KVSZ (B_ * H_ * T_ * HD_)
__device__ __half g_kh[KVSZ];    // [bh][t][e]
__device__ __half g_vt[KVSZ];    // [bh][e][t]

// ---------------------------------------------------------------------------
// helpers
// ---------------------------------------------------------------------------
__device__ __forceinline__ void split2h(float x, float y, unsigned &hi, unsigned &lo)
{
    __half hx = __float2half_rn(x), hy = __float2half_rn(y);
    __half2 h(hx, hy);
    __half2 l(__float2half_rn(x - __half2float(hx)),
              __float2half_rn(y - __half2float(hy)));
    hi = *(unsigned*)&h;
    lo = *(unsigned*)&l;
}

__device__ __forceinline__ unsigned round2h(float x, float y)
{
    __half2 h(__float2half_rn(x), __float2half_rn(y));
    return *(unsigned*)&h;
}

__device__ __forceinline__ void mma16816h(float c[4], const unsigned a[4], const unsigned b[2])
{
    asm volatile(
        "mma.sync.aligned.m16n8k16.row.col.f32.f16.f16.f32 "
        "{%0,%1,%2,%3}, {%4,%5,%6,%7}, {%8,%9}, {%0,%1,%2,%3};\n"
        : "+f"(c[0]), "+f"(c[1]), "+f"(c[2]), "+f"(c[3])
        : "r"(a[0]), "r"(a[1]), "r"(a[2]), "r"(a[3]), "r"(b[0]), "r"(b[1]));
}

__device__ __forceinline__ unsigned sptr(const void* p)
{
    return (unsigned)__cvta_generic_to_shared(p);
}

__device__ __forceinline__ void cpa16(unsigned saddr, const void* gaddr)
{
    asm volatile("cp.async.cg.shared.global [%0], [%1], 16;\n" :: "r"(saddr), "l"(gaddr));
}
__device__ __forceinline__ void cpa_commit()
{
    asm volatile("cp.async.commit_group;\n");
}
template <int N>
__device__ __forceinline__ void cpa_wait()
{
    asm volatile("cp.async.wait_group %0;\n" :: "n"(N));
}

// ---------------------------------------------------------------------------
// Split fp32 -> fp16 hi + fp16 lo (residual). Vectorized by 4.
// ---------------------------------------------------------------------------
__global__ __launch_bounds__(256) void split_fp16(
    const float* __restrict__ in, __half* __restrict__ hi,
    __half* __restrict__ lo, int n4)
{
    int i = blockIdx.x * 256 + threadIdx.x;
    if (i >= n4) return;
    float4 v = ((const float4*)in)[i];
    unsigned h0, l0, h1, l1;
    split2h(v.x, v.y, h0, l0);
    split2h(v.z, v.w, h1, l1);
    ((unsigned*)hi)[i * 2 + 0] = h0;
    ((unsigned*)hi)[i * 2 + 1] = h1;
    ((unsigned*)lo)[i * 2 + 0] = l0;
    ((unsigned*)lo)[i * 2 + 1] = l1;
}

// Round fp32 -> fp16 (single). Vectorized by 4.
__global__ __launch_bounds__(256) void round_fp16(
    const float* __restrict__ in, __half* __restrict__ out, int n4)
{
    int i = blockIdx.x * 256 + threadIdx.x;
    if (i >= n4) return;
    float4 v = ((const float4*)in)[i];
    ((unsigned*)out)[i * 2 + 0] = round2h(v.x, v.y);
    ((unsigned*)out)[i * 2 + 1] = round2h(v.z, v.w);
}

// ---------------------------------------------------------------------------
// kv_split: round K (per-bh row major) and V (per-bh TRANSPOSED) to fp16.
// grid (T/64, B*H), block 256.
// ---------------------------------------------------------------------------
__global__ __launch_bounds__(256) void kv_split(
    const float* __restrict__ qkv,
    __half* __restrict__ kh, __half* __restrict__ vt)
{
    const int jt = blockIdx.x;
    const int bh = blockIdx.y;
    const int b  = bh >> 4;
    const int h  = bh & 15;
    const int tid = threadIdx.x;

    __shared__ float sv[64][65];

    const float* base = qkv + (size_t)(b * T_ + jt * 64) * MQKV + h * HD_;

    for (int idx = tid; idx < 64 * 64; idx += 256) {
        int r = idx >> 6, e = idx & 63;
        float kx = base[(size_t)r * MQKV + D_ + e];
        kh[(size_t)(bh * T_ + jt * 64 + r) * HD_ + e] = __float2half_rn(kx);
        sv[r][e] = base[(size_t)r * MQKV + 2 * D_ + e];
    }
    __syncthreads();

    for (int idx = tid; idx < 64 * 64; idx += 256) {
        int e = idx >> 6, j = idx & 63;
        vt[((size_t)bh * HD_ + e) * T_ + jt * 64 + j] = __float2half_rn(sv[j][e]);
    }
}

// ---------------------------------------------------------------------------
// Tensor-core NT GEMM, fp16 2-term: C[N,M] = (Ahi+Alo)[N,K] @ Bh[M,K]^T.
// cp.async 2-stage double buffer, 2 CTAs/SM, scalar LDS fragment loads.
// Block 128x128, BK=32, 8 warps, warp tile 64x32.
// ---------------------------------------------------------------------------
#define BM 128
#define BN 128
#define BK 32
#define SSTR 40                         // 80B row stride, conflict-free LDS
#define MATSZ (BM * SSTR)               // 5120 elems
#define STAGESZ (3 * MATSZ)             // Ahi, Alo, Bh
#define GEMM_SMEM (2 * STAGESZ * 2)     // 61440 bytes

__global__ __launch_bounds__(256, 2) void gemm_fp16x2(
    const __half* __restrict__ Ahi, const __half* __restrict__ Alo,
    const __half* __restrict__ Bh,
    float* __restrict__ C, int Mcols)
{
    extern __shared__ __half dsm[];

    const int tid  = threadIdx.x;
    const int warp = tid >> 5;
    const int lane = tid & 31;
    const int wm = warp >> 2;
    const int wn = warp & 3;
    const int g  = lane >> 2;
    const int tg = lane & 3;
    const int rowBase = blockIdx.y * BM;
    const int colBase = blockIdx.x * BN;

    const int fr0 = tid >> 2;
    const int fc8 = (tid & 3) * 8;

    float acc[4][4][4];
#pragma unroll
    for (int im = 0; im < 4; im++)
#pragma unroll
        for (int in = 0; in < 4; in++)
#pragma unroll
            for (int q = 0; q < 4; q++) acc[im][in][q] = 0.f;

    auto fill = [&](int stage, int k0) {
        __half* base = dsm + stage * STAGESZ;
#pragma unroll
        for (int l = 0; l < 2; l++) {
            int r = fr0 + l * 64;
            unsigned soff = (unsigned)(r * SSTR + fc8);
            size_t aoff = (size_t)(rowBase + r) * K_ + k0 + fc8;
            size_t boff = (size_t)(colBase + r) * K_ + k0 + fc8;
            cpa16(sptr(base + soff),             Ahi + aoff);
            cpa16(sptr(base + MATSZ + soff),     Alo + aoff);
            cpa16(sptr(base + 2 * MATSZ + soff), Bh + boff);
        }
        cpa_commit();
    };

    const int NK = K_ / BK;
    fill(0, 0);

    for (int kt = 0; kt < NK; kt++) {
        const int stage = kt & 1;
        if (kt + 1 < NK) {
            fill(stage ^ 1, (kt + 1) * BK);
            cpa_wait<1>();
        } else {
            cpa_wait<0>();
        }
        __syncthreads();

        const __half* sAh = dsm + stage * STAGESZ;
        const __half* sAl = sAh + MATSZ;
        const __half* sB  = sAh + 2 * MATSZ;

#pragma unroll
        for (int ks = 0; ks < BK; ks += 16) {
            unsigned ahi[4][4], alo[4][4], bh[4][2];
            const int c0 = ks + tg * 2;
#pragma unroll
            for (int im = 0; im < 4; im++) {
                int ra = wm * 64 + im * 16 + g;
                ahi[im][0] = *(const unsigned*)&sAh[ra * SSTR + c0];
                ahi[im][1] = *(const unsigned*)&sAh[(ra + 8) * SSTR + c0];
                ahi[im][2] = *(const unsigned*)&sAh[ra * SSTR + c0 + 8];
                ahi[im][3] = *(const unsigned*)&sAh[(ra + 8) * SSTR + c0 + 8];
                alo[im][0] = *(const unsigned*)&sAl[ra * SSTR + c0];
                alo[im][1] = *(const unsigned*)&sAl[(ra + 8) * SSTR + c0];
                alo[im][2] = *(const unsigned*)&sAl[ra * SSTR + c0 + 8];
                alo[im][3] = *(const unsigned*)&sAl[(ra + 8) * SSTR + c0 + 8];
            }
#pragma unroll
            for (int in = 0; in < 4; in++) {
                int nb = wn * 32 + in * 8 + g;
                bh[in][0] = *(const unsigned*)&sB[nb * SSTR + c0];
                bh[in][1] = *(const unsigned*)&sB[nb * SSTR + c0 + 8];
            }
#pragma unroll
            for (int im = 0; im < 4; im++)
#pragma unroll
                for (int in = 0; in < 4; in++) {
                    mma16816h(acc[im][in], ahi[im], bh[in]);
                    mma16816h(acc[im][in], alo[im], bh[in]);
                }
        }
        __syncthreads();
    }

#pragma unroll
    for (int im = 0; im < 4; im++) {
#pragma unroll
        for (int in = 0; in < 4; in++) {
            int row = rowBase + wm * 64 + im * 16 + g;
            int col = colBase + wn * 32 + in * 8 + tg * 2;
            float2 v01 = make_float2(acc[im][in][0], acc[im][in][1]);
            float2 v23 = make_float2(acc[im][in][2], acc[im][in][3]);
            *(float2*)(C + (size_t)row * Mcols + col)       = v01;
            *(float2*)(C + (size_t)(row + 8) * Mcols + col) = v23;
        }
    }
}

// ---------------------------------------------------------------------------
// Fused flash attention, fp16 2-term: Q split / K rounded, P split / V rounded.
// Pre-rounded K/V + cp.async double buffering.
// Block = 128 q-rows (8 warps x 16 rows), j-tiles of 64.
// ---------------------------------------------------------------------------
#define FSTR 72
#define FMAT (64 * FSTR)
#define FSTAGE (2 * FMAT)                // Kh, Vt
#define FLASH_SMEM (2 * FSTAGE * 2)      // 36864 bytes

__global__ __launch_bounds__(256, 1) void flash_kernel(
    const float* __restrict__ qkv,
    const __half* __restrict__ kh, const __half* __restrict__ vt,
    __half* __restrict__ chi, __half* __restrict__ clo)
{
    extern __shared__ __half fsm[];

    const int iblk = (int)gridDim.x - 1 - (int)blockIdx.x;
    const int bh   = blockIdx.y;
    const int b    = bh >> 4;
    const int h    = bh & 15;
    const int tid  = threadIdx.x;
    const int warp = tid >> 5;
    const int lane = tid & 31;
    const int g    = lane >> 2;
    const int tg   = lane & 3;
    const int rbase = iblk * 128 + warp * 16;
    const float slope = exp2f(-(float)(h + 1) / 16.f);

    const float* qkbase = qkv + (size_t)(b * T_) * MQKV + h * HD_;
    const __half* khb = kh + (size_t)bh * T_ * HD_;
    const __half* vtb = vt + (size_t)bh * HD_ * T_;

    // Q fragments straight from gmem fp32 (once per block), fp16 hi/lo split
    unsigned qhi[4][4], qlo[4][4];
#pragma unroll
    for (int kb = 0; kb < 4; kb++)
#pragma unroll
        for (int r = 0; r < 4; r++) {
            int row = rbase + g + (r & 1) * 8;
            int col = kb * 16 + tg * 2 + (r >> 1) * 8;
            float2 v = *(const float2*)(qkbase + (size_t)row * MQKV + col);
            split2h(v.x, v.y, qhi[kb][r], qlo[kb][r]);
        }

    float acc_o[8][4];
#pragma unroll
    for (int nf = 0; nf < 8; nf++)
#pragma unroll
        for (int q = 0; q < 4; q++) acc_o[nf][q] = 0.f;
    float m0 = -CUDART_INF_F, m1 = -CUDART_INF_F;
    float l0 = 0.f, l1 = 0.f;

    const int gi0 = rbase + g;
    const int gi1 = gi0 + 8;
    const int jt_max = (iblk * 128 + 127) >> 6;

    // cp.async tile fill: 2 matrices x 64 rows x 8 chunks(16B)
    auto fill = [&](int stage, int jt) {
        __half* base = fsm + stage * FSTAGE;
        const __half* khs = khb + (size_t)(jt * 64) * HD_;
        const __half* vts = vtb + jt * 64;
#pragma unroll
        for (int l = 0; l < 2; l++) {
            int id = l * 256 + tid;
            int r  = id >> 3;
            int c8 = (id & 7) * 8;
            unsigned soff = (unsigned)(r * FSTR + c8);
            cpa16(sptr(base + soff),        khs + r * HD_ + c8);
            cpa16(sptr(base + FMAT + soff), vts + (size_t)r * T_ + c8);
        }
        cpa_commit();
    };

    fill(0, 0);

    for (int jt = 0; jt <= jt_max; jt++) {
        const int stage = jt & 1;
        if (jt + 1 <= jt_max) {
            fill(stage ^ 1, jt + 1);
            cpa_wait<1>();
        } else {
            cpa_wait<0>();
        }
        __syncthreads();

        const __half* sK = fsm + stage * FSTAGE;
        const __half* sV = sK + FMAT;

        if (jt * 64 <= rbase + 15) {
            // --- S = Q K^T (fp16 x2) ---
            float s[8][4];
#pragma unroll
            for (int nf = 0; nf < 8; nf++)
#pragma unroll
                for (int q = 0; q < 4; q++) s[nf][q] = 0.f;

#pragma unroll
            for (int kb = 0; kb < 4; kb++) {
                const int c0 = kb * 16 + tg * 2;
#pragma unroll
                for (int nf = 0; nf < 8; nf++) {
                    const int rj = nf * 8 + g;
                    unsigned kb2[2];
                    kb2[0] = *(const unsigned*)&sK[rj * FSTR + c0];
                    kb2[1] = *(const unsigned*)&sK[rj * FSTR + c0 + 8];
                    mma16816h(s[nf], qhi[kb], kb2);
                    mma16816h(s[nf], qlo[kb], kb2);
                }
            }

            // --- scale + ALiBi + causal mask ---
#pragma unroll
            for (int nf = 0; nf < 8; nf++) {
                int j0 = jt * 64 + nf * 8 + tg * 2;
                s[nf][0] = (j0     <= gi0) ? s[nf][0] * 0.125f + slope * (float)(j0     - gi0) : -CUDART_INF_F;
                s[nf][1] = (j0 + 1 <= gi0) ? s[nf][1] * 0.125f + slope * (float)(j0 + 1 - gi0) : -CUDART_INF_F;
                s[nf][2] = (j0     <= gi1) ? s[nf][2] * 0.125f + slope * (float)(j0     - gi1) : -CUDART_INF_F;
                s[nf][3] = (j0 + 1 <= gi1) ? s[nf][3] * 0.125f + slope * (float)(j0 + 1 - gi1) : -CUDART_INF_F;
            }

            // --- online softmax update ---
            float tm0 = -CUDART_INF_F, tm1 = -CUDART_INF_F;
#pragma unroll
            for (int nf = 0; nf < 8; nf++) {
                tm0 = fmaxf(tm0, fmaxf(s[nf][0], s[nf][1]));
                tm1 = fmaxf(tm1, fmaxf(s[nf][2], s[nf][3]));
            }
            tm0 = fmaxf(tm0, __shfl_xor_sync(0xffffffffu, tm0, 1));
            tm0 = fmaxf(tm0, __shfl_xor_sync(0xffffffffu, tm0, 2));
            tm1 = fmaxf(tm1, __shfl_xor_sync(0xffffffffu, tm1, 1));
            tm1 = fmaxf(tm1, __shfl_xor_sync(0xffffffffu, tm1, 2));
            float mn0 = fmaxf(m0, tm0), mn1 = fmaxf(m1, tm1);
            float a0 = __expf(m0 - mn0), a1 = __expf(m1 - mn1);

            float sum0 = 0.f, sum1 = 0.f;
#pragma unroll
            for (int nf = 0; nf < 8; nf++) {
                s[nf][0] = __expf(s[nf][0] - mn0);
                s[nf][1] = __expf(s[nf][1] - mn0);
                s[nf][2] = __expf(s[nf][2] - mn1);
                s[nf][3] = __expf(s[nf][3] - mn1);
                sum0 += s[nf][0] + s[nf][1];
                sum1 += s[nf][2] + s[nf][3];
            }
            sum0 += __shfl_xor_sync(0xffffffffu, sum0, 1);
            sum0 += __shfl_xor_sync(0xffffffffu, sum0, 2);
            sum1 += __shfl_xor_sync(0xffffffffu, sum1, 1);
            sum1 += __shfl_xor_sync(0xffffffffu, sum1, 2);
            l0 = l0 * a0 + sum0;
            l1 = l1 * a1 + sum1;
            m0 = mn0; m1 = mn1;

#pragma unroll
            for (int nf = 0; nf < 8; nf++) {
                acc_o[nf][0] *= a0; acc_o[nf][1] *= a0;
                acc_o[nf][2] *= a1; acc_o[nf][3] *= a1;
            }

            // --- O += P @ V : P split hi/lo, V rounded ---
#pragma unroll
            for (int kb = 0; kb < 4; kb++) {
                unsigned pah[4], pal[4];
                split2h(s[2 * kb][0],     s[2 * kb][1],     pah[0], pal[0]);
                split2h(s[2 * kb][2],     s[2 * kb][3],     pah[1], pal[1]);
                split2h(s[2 * kb + 1][0], s[2 * kb + 1][1], pah[2], pal[2]);
                split2h(s[2 * kb + 1][2], s[2 * kb + 1][3], pah[3], pal[3]);
                const int c0 = kb * 16 + tg * 2;
#pragma unroll
                for (int nf = 0; nf < 8; nf++) {
                    const int re = nf * 8 + g;
                    unsigned vb[2];
                    vb[0] = *(const unsigned*)&sV[re * FSTR + c0];
                    vb[1] = *(const unsigned*)&sV[re * FSTR + c0 + 8];
                    mma16816h(acc_o[nf], pah, vb);
                    mma16816h(acc_o[nf], pal, vb);
                }
            }
        }
        __syncthreads();
    }

    // --- epilogue: O /= l, write ctx as fp16 hi/lo ---
    const float r0 = 1.f / l0, r1 = 1.f / l1;
    const size_t base0 = (size_t)(b * T_ + gi0) * D_ + h * HD_;
    const size_t base1 = base0 + (size_t)8 * D_;
#pragma unroll
    for (int nf = 0; nf < 8; nf++) {
        int col = nf * 8 + tg * 2;
        unsigned uh, ul;
        split2h(acc_o[nf][0] * r0, acc_o[nf][1] * r0, uh, ul);
        *(unsigned*)(chi + base0 + col) = uh;
        *(unsigned*)(clo + base0 + col) = ul;
        split2h(acc_o[nf][2] * r1, acc_o[nf][3] * r1, uh, ul);
        *(unsigned*)(chi + base1 + col) = uh;
        *(unsigned*)(clo + base1 + col) = ul;
    }
}

// ---------------------------------------------------------------------------
extern "C" void kernel_launch(void* const* d_in, const int* in_sizes, int n_in,
                              void* d_out, int out_size)
{
    const float* x     = (const float*)d_in[0];
    const float* w_qkv = (const float*)d_in[1];
    const float* w_out = (const float*)d_in[2];
    float* out = (float*)d_out;

    float* qkv_p;
    cudaGetSymbolAddress((void**)&qkv_p, g_qkv);

    __half *xhi, *xlo, *wqh, *woh, *chi, *clo, *kh, *vt;
    cudaGetSymbolAddress((void**)&xhi, g_xhi);
    cudaGetSymbolAddress((void**)&xlo, g_xlo);
    cudaGetSymbolAddress((void**)&wqh, g_wqh);
    cudaGetSymbolAddress((void**)&woh, g_woh);
    cudaGetSymbolAddress((void**)&chi, g_chi);
    cudaGetSymbolAddress((void**)&clo, g_clo);
    cudaGetSymbolAddress((void**)&kh,  g_kh);
    cudaGetSymbolAddress((void**)&vt,  g_vt);

    // opt-in smem sizes (host-side attrs, graph-capture safe; idempotent)
    cudaFuncSetAttribute(gemm_fp16x2,  cudaFuncAttributeMaxDynamicSharedMemorySize, GEMM_SMEM);
    cudaFuncSetAttribute(flash_kernel, cudaFuncAttributeMaxDynamicSharedMemorySize, FLASH_SMEM);

    // 0) fp16 conversions: x split hi/lo; weights rounded
    {
        int n4 = NTOK * K_ / 4;
        split_fp16<<<(n4 + 255) / 256, 256>>>(x, xhi, xlo, n4);
        n4 = MQKV * K_ / 4;
        round_fp16<<<(n4 + 255) / 256, 256>>>(w_qkv, wqh, n4);
        n4 = D_ * K_ / 4;
        round_fp16<<<(n4 + 255) / 256, 256>>>(w_out, woh, n4);
    }

    // 1) QKV projection (fp16 x2): [4096,1024] @ [3072,1024]^T
    gemm_fp16x2<<<dim3(MQKV / BN, NTOK / BM), 256, GEMM_SMEM>>>(xhi, xlo, wqh, qkv_p, MQKV);

    // 1b) pre-round K (row major) and V (transposed) to fp16
    kv_split<<<dim3(T_ / 64, B_ * H_), 256>>>(qkv_p, kh, vt);

    // 2) Fused flash attention (cp.async double-buffered K/V tiles)
    flash_kernel<<<dim3(T_ / 128, B_ * H_), 256, FLASH_SMEM>>>(qkv_p, kh, vt, chi, clo);

    // 3) Output projection (fp16 x2)
    gemm_fp16x2<<<dim3(D_ / BN, NTOK / BM), 256, GEMM_SMEM>>>(chi, clo, woh, out, D_);
}

// round 17
// speedup vs baseline: 2.6362x; 1.0087x over previous
#include <cuda_runtime.h>
#include <cuda_fp16.h>
#include <math_constants.h>
#include <cstdint>

// Fixed problem shapes
#define B_ 2
#define T_ 2048
#define D_ 1024
#define H_ 16
#define HD_ 64
#define NTOK (B_ * T_)          // 4096
#define MQKV (3 * D_)           // 3072
#define K_ 1024

// Scratch (allocation-free rule: __device__ globals)
__device__ float g_qkv[NTOK * MQKV];                 // [4096, 3072] fp32 q|k|v

// fp16 scratch. "int" buffers are hi/lo INTERLEAVED: per k-pair p (cols 2p,2p+1)
// halves [4p..4p+3] = hi(2p),hi(2p+1),lo(2p),lo(2p+1). Row length 2*K_ halves.
__device__ __half g_xint[NTOK * 2 * K_];             // x split-interleaved (A of qkv gemm)
__device__ __half g_cint[NTOK * 2 * K_];             // ctx split-interleaved (A of out gemm)
__device__ __half g_wqh[MQKV * K_];                  // w_qkv rounded (B)
__device__ __half g_woh[D_ * K_];                    // w_out rounded (B)

// pre-rounded K (row-major per bh) and V (transposed per bh) for flash
#define KVSZ (B_ * H_ * T_ * HD_)
__device__ __half g_kh[KVSZ];    // [bh][t][e]
__device__ __half g_vt[KVSZ];    // [bh][e][t]

// ---------------------------------------------------------------------------
// helpers
// ---------------------------------------------------------------------------
__device__ __forceinline__ void split2h(float x, float y, unsigned &hi, unsigned &lo)
{
    __half hx = __float2half_rn(x), hy = __float2half_rn(y);
    __half2 h(hx, hy);
    __half2 l(__float2half_rn(x - __half2float(hx)),
              __float2half_rn(y - __half2float(hy)));
    hi = *(unsigned*)&h;
    lo = *(unsigned*)&l;
}

__device__ __forceinline__ unsigned round2h(float x, float y)
{
    __half2 h(__float2half_rn(x), __float2half_rn(y));
    return *(unsigned*)&h;
}

__device__ __forceinline__ void mma16816h(float c[4], const unsigned a[4], const unsigned b[2])
{
    asm volatile(
        "mma.sync.aligned.m16n8k16.row.col.f32.f16.f16.f32 "
        "{%0,%1,%2,%3}, {%4,%5,%6,%7}, {%8,%9}, {%0,%1,%2,%3};\n"
        : "+f"(c[0]), "+f"(c[1]), "+f"(c[2]), "+f"(c[3])
        : "r"(a[0]), "r"(a[1]), "r"(a[2]), "r"(a[3]), "r"(b[0]), "r"(b[1]));
}

__device__ __forceinline__ unsigned sptr(const void* p)
{
    return (unsigned)__cvta_generic_to_shared(p);
}

__device__ __forceinline__ void cpa16(unsigned saddr, const void* gaddr)
{
    asm volatile("cp.async.cg.shared.global [%0], [%1], 16;\n" :: "r"(saddr), "l"(gaddr));
}
__device__ __forceinline__ void cpa_commit()
{
    asm volatile("cp.async.commit_group;\n");
}
template <int N>
__device__ __forceinline__ void cpa_wait()
{
    asm volatile("cp.async.wait_group %0;\n" :: "n"(N));
}

// ---------------------------------------------------------------------------
// Split fp32 -> fp16 hi/lo INTERLEAVED ([h01, l01, h23, l23] per 4 floats).
// ---------------------------------------------------------------------------
__global__ __launch_bounds__(256) void split_fp16i(
    const float* __restrict__ in, __half* __restrict__ outi, int n4)
{
    int i = blockIdx.x * 256 + threadIdx.x;
    if (i >= n4) return;
    float4 v = ((const float4*)in)[i];
    unsigned h0, l0, h1, l1;
    split2h(v.x, v.y, h0, l0);
    split2h(v.z, v.w, h1, l1);
    uint4 o; o.x = h0; o.y = l0; o.z = h1; o.w = l1;
    ((uint4*)outi)[i] = o;
}

// Round fp32 -> fp16 (single). Vectorized by 4.
__global__ __launch_bounds__(256) void round_fp16(
    const float* __restrict__ in, __half* __restrict__ out, int n4)
{
    int i = blockIdx.x * 256 + threadIdx.x;
    if (i >= n4) return;
    float4 v = ((const float4*)in)[i];
    ((unsigned*)out)[i * 2 + 0] = round2h(v.x, v.y);
    ((unsigned*)out)[i * 2 + 1] = round2h(v.z, v.w);
}

// ---------------------------------------------------------------------------
// kv_split: round K (per-bh row major) and V (per-bh TRANSPOSED) to fp16.
// ---------------------------------------------------------------------------
__global__ __launch_bounds__(256) void kv_split(
    const float* __restrict__ qkv,
    __half* __restrict__ kh, __half* __restrict__ vt)
{
    const int jt = blockIdx.x;
    const int bh = blockIdx.y;
    const int b  = bh >> 4;
    const int h  = bh & 15;
    const int tid = threadIdx.x;

    __shared__ float sv[64][65];

    const float* base = qkv + (size_t)(b * T_ + jt * 64) * MQKV + h * HD_;

    for (int idx = tid; idx < 64 * 64; idx += 256) {
        int r = idx >> 6, e = idx & 63;
        float kx = base[(size_t)r * MQKV + D_ + e];
        kh[(size_t)(bh * T_ + jt * 64 + r) * HD_ + e] = __float2half_rn(kx);
        sv[r][e] = base[(size_t)r * MQKV + 2 * D_ + e];
    }
    __syncthreads();

    for (int idx = tid; idx < 64 * 64; idx += 256) {
        int e = idx >> 6, j = idx & 63;
        vt[((size_t)bh * HD_ + e) * T_ + jt * 64 + j] = __float2half_rn(sv[j][e]);
    }
}

// ---------------------------------------------------------------------------
// Tensor-core NT GEMM, fp16 2-term: C = (Ahi+Alo) @ B^T, A hi/lo interleaved.
// 3-stage cp.async pipeline, ONE barrier per k-tile, 2 CTAs/SM.
// Block 128x128, BK=32, 8 warps, warp tile 64x32. A frag loads are LDS.64.
// ---------------------------------------------------------------------------
#define BM 128
#define BN 128
#define BK 32
#define ASTR 80                          // halves/row (160B): LDS.64 conflict-free
#define BSTR 40                          // halves/row (80B):  LDS.32 conflict-free
#define AMAT (BM * ASTR)                 // 10240 halves
#define STAGE_H (AMAT + BN * BSTR)       // 15360 halves
#define GEMM_SMEM (3 * STAGE_H * 2)      // 92160 bytes

__global__ __launch_bounds__(256, 2) void gemm_fp16x2(
    const __half* __restrict__ Aint, const __half* __restrict__ Bh,
    float* __restrict__ C, int Mcols)
{
    extern __shared__ __half dsm[];

    const int tid  = threadIdx.x;
    const int warp = tid >> 5;
    const int lane = tid & 31;
    const int wm = warp >> 2;
    const int wn = warp & 3;
    const int g  = lane >> 2;
    const int tg = lane & 3;
    const int rowBase = blockIdx.y * BM;
    const int colBase = blockIdx.x * BN;

    float acc[4][4][4];
#pragma unroll
    for (int im = 0; im < 4; im++)
#pragma unroll
        for (int in = 0; in < 4; in++)
#pragma unroll
            for (int q = 0; q < 4; q++) acc[im][in][q] = 0.f;

    // fill: A interleaved (8 chunks/row of 16B) + B (4 chunks/row). 1536 chunks.
    auto fill = [&](int slab, int k0) {
        __half* base = dsm + (slab % 3) * STAGE_H;
#pragma unroll
        for (int l = 0; l < 6; l++) {
            int id = l * 256 + tid;              // 0..1535
            if (id < 1024) {
                int r = id >> 3, c = id & 7;
                cpa16(sptr(base + r * ASTR + c * 8),
                      Aint + (size_t)(rowBase + r) * (2 * K_) + 2 * k0 + c * 8);
            } else {
                int j = id - 1024;
                int r = j >> 2, c = j & 3;
                cpa16(sptr(base + AMAT + r * BSTR + c * 8),
                      Bh + (size_t)(colBase + r) * K_ + k0 + c * 8);
            }
        }
        cpa_commit();
    };

    const int NK = K_ / BK;   // 32
    fill(0, 0);
    fill(1, BK);

    for (int kt = 0; kt < NK; kt++) {
        if (kt + 1 < NK) cpa_wait<1>(); else cpa_wait<0>();
        __syncthreads();                       // all warps done with stage kt-1
        if (kt + 2 < NK) fill(kt + 2, (kt + 2) * BK);

        const __half* sA = dsm + (kt % 3) * STAGE_H;
        const __half* sB = sA + AMAT;

#pragma unroll
        for (int ks = 0; ks < BK; ks += 16) {
            unsigned ahi[4][4], alo[4][4], bh[4][2];
            const int aoff0 = 2 * ks + 4 * tg;   // halves: pair p0 = ks/2 + tg
            const int c0 = ks + tg * 2;
#pragma unroll
            for (int im = 0; im < 4; im++) {
                int ra = wm * 64 + im * 16 + g;
                uint2 v0 = *(const uint2*)&sA[ra * ASTR + aoff0];
                uint2 v1 = *(const uint2*)&sA[(ra + 8) * ASTR + aoff0];
                uint2 v2 = *(const uint2*)&sA[ra * ASTR + aoff0 + 16];
                uint2 v3 = *(const uint2*)&sA[(ra + 8) * ASTR + aoff0 + 16];
                ahi[im][0] = v0.x; alo[im][0] = v0.y;
                ahi[im][1] = v1.x; alo[im][1] = v1.y;
                ahi[im][2] = v2.x; alo[im][2] = v2.y;
                ahi[im][3] = v3.x; alo[im][3] = v3.y;
            }
#pragma unroll
            for (int in = 0; in < 4; in++) {
                int nb = wn * 32 + in * 8 + g;
                bh[in][0] = *(const unsigned*)&sB[nb * BSTR + c0];
                bh[in][1] = *(const unsigned*)&sB[nb * BSTR + c0 + 8];
            }
#pragma unroll
            for (int im = 0; im < 4; im++)
#pragma unroll
                for (int in = 0; in < 4; in++) {
                    mma16816h(acc[im][in], ahi[im], bh[in]);
                    mma16816h(acc[im][in], alo[im], bh[in]);
                }
        }
    }

#pragma unroll
    for (int im = 0; im < 4; im++) {
#pragma unroll
        for (int in = 0; in < 4; in++) {
            int row = rowBase + wm * 64 + im * 16 + g;
            int col = colBase + wn * 32 + in * 8 + tg * 2;
            float2 v01 = make_float2(acc[im][in][0], acc[im][in][1]);
            float2 v23 = make_float2(acc[im][in][2], acc[im][in][3]);
            *(float2*)(C + (size_t)row * Mcols + col)       = v01;
            *(float2*)(C + (size_t)(row + 8) * Mcols + col) = v23;
        }
    }
}

// ---------------------------------------------------------------------------
// Fused flash attention, fp16 2-term, 3-stage cp.async, ONE barrier per tile.
// Q split / K rounded, P split / V rounded. Writes ctx split-INTERLEAVED.
// Block = 128 q-rows (8 warps x 16 rows), j-tiles of 64.
// ---------------------------------------------------------------------------
#define FSTR 72
#define FMAT (64 * FSTR)
#define FSTAGE (2 * FMAT)                // Kh, Vt
#define FLASH_SMEM (3 * FSTAGE * 2)      // 55296 bytes

__global__ __launch_bounds__(256, 1) void flash_kernel(
    const float* __restrict__ qkv,
    const __half* __restrict__ kh, const __half* __restrict__ vt,
    __half* __restrict__ cint)
{
    extern __shared__ __half fsm[];

    const int iblk = (int)gridDim.x - 1 - (int)blockIdx.x;
    const int bh   = blockIdx.y;
    const int b    = bh >> 4;
    const int h    = bh & 15;
    const int tid  = threadIdx.x;
    const int warp = tid >> 5;
    const int lane = tid & 31;
    const int g    = lane >> 2;
    const int tg   = lane & 3;
    const int rbase = iblk * 128 + warp * 16;
    const float slope = exp2f(-(float)(h + 1) / 16.f);

    const float* qkbase = qkv + (size_t)(b * T_) * MQKV + h * HD_;
    const __half* khb = kh + (size_t)bh * T_ * HD_;
    const __half* vtb = vt + (size_t)bh * HD_ * T_;

    unsigned qhi[4][4], qlo[4][4];
#pragma unroll
    for (int kb = 0; kb < 4; kb++)
#pragma unroll
        for (int r = 0; r < 4; r++) {
            int row = rbase + g + (r & 1) * 8;
            int col = kb * 16 + tg * 2 + (r >> 1) * 8;
            float2 v = *(const float2*)(qkbase + (size_t)row * MQKV + col);
            split2h(v.x, v.y, qhi[kb][r], qlo[kb][r]);
        }

    float acc_o[8][4];
#pragma unroll
    for (int nf = 0; nf < 8; nf++)
#pragma unroll
        for (int q = 0; q < 4; q++) acc_o[nf][q] = 0.f;
    float m0 = -CUDART_INF_F, m1 = -CUDART_INF_F;
    float l0 = 0.f, l1 = 0.f;

    const int gi0 = rbase + g;
    const int gi1 = gi0 + 8;
    const int jt_max = (iblk * 128 + 127) >> 6;

    auto fill = [&](int jt) {
        __half* base = fsm + (jt % 3) * FSTAGE;
        const __half* khs = khb + (size_t)(jt * 64) * HD_;
        const __half* vts = vtb + jt * 64;
#pragma unroll
        for (int l = 0; l < 2; l++) {
            int id = l * 256 + tid;
            int r  = id >> 3;
            int c8 = (id & 7) * 8;
            unsigned soff = (unsigned)(r * FSTR + c8);
            cpa16(sptr(base + soff),        khs + r * HD_ + c8);
            cpa16(sptr(base + FMAT + soff), vts + (size_t)r * T_ + c8);
        }
        cpa_commit();
    };

    fill(0);
    if (jt_max >= 1) fill(1);

    for (int jt = 0; jt <= jt_max; jt++) {
        if (jt + 1 <= jt_max) cpa_wait<1>(); else cpa_wait<0>();
        __syncthreads();
        if (jt + 2 <= jt_max) fill(jt + 2);

        const __half* sK = fsm + (jt % 3) * FSTAGE;
        const __half* sV = sK + FMAT;

        if (jt * 64 <= rbase + 15) {
            float s[8][4];
#pragma unroll
            for (int nf = 0; nf < 8; nf++)
#pragma unroll
                for (int q = 0; q < 4; q++) s[nf][q] = 0.f;

#pragma unroll
            for (int kb = 0; kb < 4; kb++) {
                const int c0 = kb * 16 + tg * 2;
#pragma unroll
                for (int nf = 0; nf < 8; nf++) {
                    const int rj = nf * 8 + g;
                    unsigned kb2[2];
                    kb2[0] = *(const unsigned*)&sK[rj * FSTR + c0];
                    kb2[1] = *(const unsigned*)&sK[rj * FSTR + c0 + 8];
                    mma16816h(s[nf], qhi[kb], kb2);
                    mma16816h(s[nf], qlo[kb], kb2);
                }
            }

#pragma unroll
            for (int nf = 0; nf < 8; nf++) {
                int j0 = jt * 64 + nf * 8 + tg * 2;
                s[nf][0] = (j0     <= gi0) ? s[nf][0] * 0.125f + slope * (float)(j0     - gi0) : -CUDART_INF_F;
                s[nf][1] = (j0 + 1 <= gi0) ? s[nf][1] * 0.125f + slope * (float)(j0 + 1 - gi0) : -CUDART_INF_F;
                s[nf][2] = (j0     <= gi1) ? s[nf][2] * 0.125f + slope * (float)(j0     - gi1) : -CUDART_INF_F;
                s[nf][3] = (j0 + 1 <= gi1) ? s[nf][3] * 0.125f + slope * (float)(j0 + 1 - gi1) : -CUDART_INF_F;
            }

            float tm0 = -CUDART_INF_F, tm1 = -CUDART_INF_F;
#pragma unroll
            for (int nf = 0; nf < 8; nf++) {
                tm0 = fmaxf(tm0, fmaxf(s[nf][0], s[nf][1]));
                tm1 = fmaxf(tm1, fmaxf(s[nf][2], s[nf][3]));
            }
            tm0 = fmaxf(tm0, __shfl_xor_sync(0xffffffffu, tm0, 1));
            tm0 = fmaxf(tm0, __shfl_xor_sync(0xffffffffu, tm0, 2));
            tm1 = fmaxf(tm1, __shfl_xor_sync(0xffffffffu, tm1, 1));
            tm1 = fmaxf(tm1, __shfl_xor_sync(0xffffffffu, tm1, 2));
            float mn0 = fmaxf(m0, tm0), mn1 = fmaxf(m1, tm1);
            float a0 = __expf(m0 - mn0), a1 = __expf(m1 - mn1);

            float sum0 = 0.f, sum1 = 0.f;
#pragma unroll
            for (int nf = 0; nf < 8; nf++) {
                s[nf][0] = __expf(s[nf][0] - mn0);
                s[nf][1] = __expf(s[nf][1] - mn0);
                s[nf][2] = __expf(s[nf][2] - mn1);
                s[nf][3] = __expf(s[nf][3] - mn1);
                sum0 += s[nf][0] + s[nf][1];
                sum1 += s[nf][2] + s[nf][3];
            }
            sum0 += __shfl_xor_sync(0xffffffffu, sum0, 1);
            sum0 += __shfl_xor_sync(0xffffffffu, sum0, 2);
            sum1 += __shfl_xor_sync(0xffffffffu, sum1, 1);
            sum1 += __shfl_xor_sync(0xffffffffu, sum1, 2);
            l0 = l0 * a0 + sum0;
            l1 = l1 * a1 + sum1;
            m0 = mn0; m1 = mn1;

#pragma unroll
            for (int nf = 0; nf < 8; nf++) {
                acc_o[nf][0] *= a0; acc_o[nf][1] *= a0;
                acc_o[nf][2] *= a1; acc_o[nf][3] *= a1;
            }

#pragma unroll
            for (int kb = 0; kb < 4; kb++) {
                unsigned pah[4], pal[4];
                split2h(s[2 * kb][0],     s[2 * kb][1],     pah[0], pal[0]);
                split2h(s[2 * kb][2],     s[2 * kb][3],     pah[1], pal[1]);
                split2h(s[2 * kb + 1][0], s[2 * kb + 1][1], pah[2], pal[2]);
                split2h(s[2 * kb + 1][2], s[2 * kb + 1][3], pah[3], pal[3]);
                const int c0 = kb * 16 + tg * 2;
#pragma unroll
                for (int nf = 0; nf < 8; nf++) {
                    const int re = nf * 8 + g;
                    unsigned vb[2];
                    vb[0] = *(const unsigned*)&sV[re * FSTR + c0];
                    vb[1] = *(const unsigned*)&sV[re * FSTR + c0 + 8];
                    mma16816h(acc_o[nf], pah, vb);
                    mma16816h(acc_o[nf], pal, vb);
                }
            }
        }
    }

    // --- epilogue: O /= l, write ctx split-INTERLEAVED ([.. 2*col: hi, 2*col+2: lo ..]) ---
    const float r0 = 1.f / l0, r1 = 1.f / l1;
    const size_t base0 = (size_t)(b * T_ + gi0) * (2 * D_) + 2 * (h * HD_);
    const size_t base1 = base0 + (size_t)8 * 2 * D_;
#pragma unroll
    for (int nf = 0; nf < 8; nf++) {
        int col2 = 2 * (nf * 8 + tg * 2);
        unsigned uh, ul;
        split2h(acc_o[nf][0] * r0, acc_o[nf][1] * r0, uh, ul);
        *(unsigned*)(cint + base0 + col2)     = uh;
        *(unsigned*)(cint + base0 + col2 + 2) = ul;
        split2h(acc_o[nf][2] * r1, acc_o[nf][3] * r1, uh, ul);
        *(unsigned*)(cint + base1 + col2)     = uh;
        *(unsigned*)(cint + base1 + col2 + 2) = ul;
    }
}

// ---------------------------------------------------------------------------
extern "C" void kernel_launch(void* const* d_in, const int* in_sizes, int n_in,
                              void* d_out, int out_size)
{
    const float* x     = (const float*)d_in[0];
    const float* w_qkv = (const float*)d_in[1];
    const float* w_out = (const float*)d_in[2];
    float* out = (float*)d_out;

    float* qkv_p;
    cudaGetSymbolAddress((void**)&qkv_p, g_qkv);

    __half *xint, *cint, *wqh, *woh, *kh, *vt;
    cudaGetSymbolAddress((void**)&xint, g_xint);
    cudaGetSymbolAddress((void**)&cint, g_cint);
    cudaGetSymbolAddress((void**)&wqh,  g_wqh);
    cudaGetSymbolAddress((void**)&woh,  g_woh);
    cudaGetSymbolAddress((void**)&kh,   g_kh);
    cudaGetSymbolAddress((void**)&vt,   g_vt);

    // opt-in smem sizes (host-side attrs, graph-capture safe; idempotent)
    cudaFuncSetAttribute(gemm_fp16x2,  cudaFuncAttributeMaxDynamicSharedMemorySize, GEMM_SMEM);
    cudaFuncSetAttribute(flash_kernel, cudaFuncAttributeMaxDynamicSharedMemorySize, FLASH_SMEM);

    // 0) fp16 conversions: x split-interleaved; weights rounded
    {
        int n4 = NTOK * K_ / 4;
        split_fp16i<<<(n4 + 255) / 256, 256>>>(x, xint, n4);
        n4 = MQKV * K_ / 4;
        round_fp16<<<(n4 + 255) / 256, 256>>>(w_qkv, wqh, n4);
        n4 = D_ * K_ / 4;
        round_fp16<<<(n4 + 255) / 256, 256>>>(w_out, woh, n4);
    }

    // 1) QKV projection (fp16 x2): [4096,1024] @ [3072,1024]^T
    gemm_fp16x2<<<dim3(MQKV / BN, NTOK / BM), 256, GEMM_SMEM>>>(xint, wqh, qkv_p, MQKV);

    // 1b) pre-round K (row major) and V (transposed) to fp16
    kv_split<<<dim3(T_ / 64, B_ * H_), 256>>>(qkv_p, kh, vt);

    // 2) Fused flash attention (3-stage cp.async), writes ctx split-interleaved
    flash_kernel<<<dim3(T_ / 128, B_ * H_), 256, FLASH_SMEM>>>(qkv_p, kh, vt, cint);

    // 3) Output projection (fp16 x2)
    gemm_fp16x2<<<dim3(D_ / BN, NTOK / BM), 256, GEMM_SMEM>>>(cint, woh, out, D_);
}